// round 2
// baseline (speedup 1.0000x reference)
#include <cuda_runtime.h>
#include <math.h>

// Problem constants
#define BB 4
#define DD 8
#define FF 256
#define CC 512
#define RR 64
#define NKEY 2048            // D*F
#define MTOT 8192            // B*D*F
#define LN_EPS 1e-3f

// ---------------- scratch (static device memory; no allocations) ----------------
__device__ float g_Q  [BB * NKEY * RR];          // 2 MB
__device__ float g_K  [BB * NKEY * RR];          // 2 MB
__device__ float g_V  [BB * NKEY * CC];          // 16.8 MB
__device__ float g_E  [(long)BB * NKEY * NKEY];  // 67 MB
__device__ float g_A2 [BB * NKEY * FF];          // 8.4 MB
__device__ float g_ATT[BB * NKEY * CC];          // 16.8 MB
__device__ float g_Y1 [BB * NKEY * CC];          // 16.8 MB
__device__ float g_T  [BB * NKEY * CC];          // 16.8 MB

// ---------------------------------------------------------------------------
// Generic NN GEMM: C[M,N] = A[M,K] @ B[K,N] (+bias), optional batch strides.
// BM=BN=64, BK=16, 256 threads, 4x4 register tile per thread.
// All dims assumed divisible by tile sizes (true for this problem).
// ---------------------------------------------------------------------------
__global__ void gemm_nn(const float* __restrict__ A,
                        const float* __restrict__ B,
                        const float* __restrict__ bias,
                        float* __restrict__ C,
                        int M, int K, int N,
                        long sA, long sB, long sC)
{
    const int bz = blockIdx.z;
    A += (long)bz * sA;
    B += (long)bz * sB;
    C += (long)bz * sC;

    __shared__ float As[16][64];
    __shared__ float Bs[16][64];

    const int tid = threadIdx.x;       // 0..255
    const int tx = tid & 15;           // 0..15
    const int ty = tid >> 4;           // 0..15
    const int rowBase = blockIdx.y * 64;
    const int colBase = blockIdx.x * 64;

    // A-load mapping: 64 rows x 16 k, float4 per thread
    const int aRow  = tid >> 2;           // 0..63
    const int aCol4 = (tid & 3) << 2;     // 0,4,8,12
    // B-load mapping: 16 k x 64 cols, float4 per thread
    const int bRow  = tid >> 4;           // 0..15
    const int bCol4 = (tid & 15) << 2;    // 0..60

    float acc[4][4] = {};

    for (int k0 = 0; k0 < K; k0 += 16) {
        float4 av = *(const float4*)(A + (long)(rowBase + aRow) * K + k0 + aCol4);
        As[aCol4 + 0][aRow] = av.x;
        As[aCol4 + 1][aRow] = av.y;
        As[aCol4 + 2][aRow] = av.z;
        As[aCol4 + 3][aRow] = av.w;
        *(float4*)&Bs[bRow][bCol4] =
            *(const float4*)(B + (long)(k0 + bRow) * N + colBase + bCol4);
        __syncthreads();

#pragma unroll
        for (int kk = 0; kk < 16; kk++) {
            float4 a4 = *(const float4*)&As[kk][ty << 2];
            float4 b4 = *(const float4*)&Bs[kk][tx << 2];
            float ar[4] = {a4.x, a4.y, a4.z, a4.w};
            float br[4] = {b4.x, b4.y, b4.z, b4.w};
#pragma unroll
            for (int i = 0; i < 4; i++)
#pragma unroll
                for (int j = 0; j < 4; j++)
                    acc[i][j] = fmaf(ar[i], br[j], acc[i][j]);
        }
        __syncthreads();
    }

    float4 b4 = make_float4(0.f, 0.f, 0.f, 0.f);
    if (bias) b4 = *(const float4*)(bias + colBase + (tx << 2));
#pragma unroll
    for (int i = 0; i < 4; i++) {
        const long row = rowBase + (ty << 2) + i;
        float4 o;
        o.x = acc[i][0] + b4.x;
        o.y = acc[i][1] + b4.y;
        o.z = acc[i][2] + b4.z;
        o.w = acc[i][3] + b4.w;
        *(float4*)(C + row * N + colBase + (tx << 2)) = o;
    }
}

// ---------------------------------------------------------------------------
// NT GEMM for scores: E[M,N] = A[M,Kd] @ B[N,Kd]^T, batched over z.
// Same tiling; B tile is transpose-loaded into smem.
// ---------------------------------------------------------------------------
__global__ void gemm_nt(const float* __restrict__ A,
                        const float* __restrict__ B,
                        float* __restrict__ C,
                        int M, int Kd, int N,
                        long sA, long sB, long sC)
{
    const int bz = blockIdx.z;
    A += (long)bz * sA;
    B += (long)bz * sB;
    C += (long)bz * sC;

    __shared__ float As[16][64];
    __shared__ float Bs[16][64];

    const int tid = threadIdx.x;
    const int tx = tid & 15;
    const int ty = tid >> 4;
    const int rowBase = blockIdx.y * 64;
    const int colBase = blockIdx.x * 64;

    const int aRow  = tid >> 2;        // 0..63
    const int aCol4 = (tid & 3) << 2;  // 0..12

    float acc[4][4] = {};

    for (int k0 = 0; k0 < Kd; k0 += 16) {
        float4 av = *(const float4*)(A + (long)(rowBase + aRow) * Kd + k0 + aCol4);
        As[aCol4 + 0][aRow] = av.x;
        As[aCol4 + 1][aRow] = av.y;
        As[aCol4 + 2][aRow] = av.z;
        As[aCol4 + 3][aRow] = av.w;
        // B tile: rows are key indices, transpose into Bs[k][n]
        float4 bv = *(const float4*)(B + (long)(colBase + aRow) * Kd + k0 + aCol4);
        Bs[aCol4 + 0][aRow] = bv.x;
        Bs[aCol4 + 1][aRow] = bv.y;
        Bs[aCol4 + 2][aRow] = bv.z;
        Bs[aCol4 + 3][aRow] = bv.w;
        __syncthreads();

#pragma unroll
        for (int kk = 0; kk < 16; kk++) {
            float4 a4 = *(const float4*)&As[kk][ty << 2];
            float4 b4 = *(const float4*)&Bs[kk][tx << 2];
            float ar[4] = {a4.x, a4.y, a4.z, a4.w};
            float br[4] = {b4.x, b4.y, b4.z, b4.w};
#pragma unroll
            for (int i = 0; i < 4; i++)
#pragma unroll
                for (int j = 0; j < 4; j++)
                    acc[i][j] = fmaf(ar[i], br[j], acc[i][j]);
        }
        __syncthreads();
    }

#pragma unroll
    for (int i = 0; i < 4; i++) {
        const long row = rowBase + (ty << 2) + i;
        *(float4*)(C + row * N + colBase + (tx << 2)) =
            make_float4(acc[i][0], acc[i][1], acc[i][2], acc[i][3]);
    }
}

// ---------------------------------------------------------------------------
// Softmax over 2048 keys + fold over key-depth g:
//   a2[row, jf] = sum_g exp(e[row, g*256+jf] - m) / Z
// One block (256 threads) per query row; thread t owns jf = t across all g.
// ---------------------------------------------------------------------------
__global__ void softmax_fold(const float* __restrict__ E, float* __restrict__ A2)
{
    const long row = blockIdx.x;
    const float* e = E + row * (long)NKEY;
    const int t = threadIdx.x;

    float v[DD];
    float m = -INFINITY;
#pragma unroll
    for (int g = 0; g < DD; g++) {
        v[g] = e[g * FF + t];
        m = fmaxf(m, v[g]);
    }

    __shared__ float red[256];
    red[t] = m;
    __syncthreads();
#pragma unroll
    for (int s = 128; s > 0; s >>= 1) {
        if (t < s) red[t] = fmaxf(red[t], red[t + s]);
        __syncthreads();
    }
    m = red[0];
    __syncthreads();

    float a = 0.f;
#pragma unroll
    for (int g = 0; g < DD; g++)
        a += __expf(v[g] - m);

    red[t] = a;
    __syncthreads();
#pragma unroll
    for (int s = 128; s > 0; s >>= 1) {
        if (t < s) red[t] += red[t + s];
        __syncthreads();
    }
    const float Z = red[0];

    A2[row * (long)FF + t] = a / Z;
}

// ---------------------------------------------------------------------------
// out_row = LayerNorm(A_row + f(B_row)) * gamma + beta, f = relu if relu_b.
// One block (128 threads, float4 each) per row of 512 channels.
// ---------------------------------------------------------------------------
__global__ void add_ln(const float* __restrict__ A, const float* __restrict__ B,
                       const float* __restrict__ gamma, const float* __restrict__ beta,
                       float* __restrict__ out, int relu_b)
{
    const long row = blockIdx.x;
    const int t = threadIdx.x;  // 0..127

    float4 a4 = ((const float4*)(A + row * CC))[t];
    float4 b4 = ((const float4*)(B + row * CC))[t];
    if (relu_b) {
        b4.x = fmaxf(b4.x, 0.f);
        b4.y = fmaxf(b4.y, 0.f);
        b4.z = fmaxf(b4.z, 0.f);
        b4.w = fmaxf(b4.w, 0.f);
    }
    float x0 = a4.x + b4.x, x1 = a4.y + b4.y, x2 = a4.z + b4.z, x3 = a4.w + b4.w;

    float s  = x0 + x1 + x2 + x3;
    float sq = x0 * x0 + x1 * x1 + x2 * x2 + x3 * x3;
#pragma unroll
    for (int o = 16; o > 0; o >>= 1) {
        s  += __shfl_xor_sync(0xFFFFFFFFu, s,  o);
        sq += __shfl_xor_sync(0xFFFFFFFFu, sq, o);
    }
    __shared__ float ss[4], qq[4];
    const int w = t >> 5, l = t & 31;
    if (l == 0) { ss[w] = s; qq[w] = sq; }
    __syncthreads();
    s  = ss[0] + ss[1] + ss[2] + ss[3];
    sq = qq[0] + qq[1] + qq[2] + qq[3];

    const float mean = s * (1.f / CC);
    const float var  = sq * (1.f / CC) - mean * mean;
    const float r    = rsqrtf(var + LN_EPS);

    float4 g4  = ((const float4*)gamma)[t];
    float4 be4 = ((const float4*)beta)[t];
    float4 o4;
    o4.x = (x0 - mean) * r * g4.x + be4.x;
    o4.y = (x1 - mean) * r * g4.y + be4.y;
    o4.z = (x2 - mean) * r * g4.z + be4.z;
    o4.w = (x3 - mean) * r * g4.w + be4.w;
    ((float4*)(out + row * CC))[t] = o4;
}

// ---------------------------------------------------------------------------
extern "C" void kernel_launch(void* const* d_in, const int* in_sizes, int n_in,
                              void* d_out, int out_size)
{
    const float* x  = (const float*)d_in[0];
    const float* wq = (const float*)d_in[1];
    const float* bq = (const float*)d_in[2];
    const float* wk = (const float*)d_in[3];
    const float* bk = (const float*)d_in[4];
    const float* wv = (const float*)d_in[5];
    const float* bv = (const float*)d_in[6];
    const float* wm = (const float*)d_in[7];
    const float* bm = (const float*)d_in[8];
    const float* g1 = (const float*)d_in[9];
    const float* b1 = (const float*)d_in[10];
    const float* g2 = (const float*)d_in[11];
    const float* b2 = (const float*)d_in[12];
    float* out = (float*)d_out;

    float *Q, *K, *V, *E, *A2, *ATT, *Y1, *T;
    cudaGetSymbolAddress((void**)&Q,   g_Q);
    cudaGetSymbolAddress((void**)&K,   g_K);
    cudaGetSymbolAddress((void**)&V,   g_V);
    cudaGetSymbolAddress((void**)&E,   g_E);
    cudaGetSymbolAddress((void**)&A2,  g_A2);
    cudaGetSymbolAddress((void**)&ATT, g_ATT);
    cudaGetSymbolAddress((void**)&Y1,  g_Y1);
    cudaGetSymbolAddress((void**)&T,   g_T);

    // 1) Q/K/V projections: [8192,512] @ [512,{64,64,512}]
    gemm_nn<<<dim3(RR / 64, MTOT / 64, 1), 256>>>(x, wq, bq, Q, MTOT, CC, RR, 0, 0, 0);
    gemm_nn<<<dim3(RR / 64, MTOT / 64, 1), 256>>>(x, wk, bk, K, MTOT, CC, RR, 0, 0, 0);
    gemm_nn<<<dim3(CC / 64, MTOT / 64, 1), 256>>>(x, wv, bv, V, MTOT, CC, CC, 0, 0, 0);

    // 2) scores: per batch E = Q @ K^T  [2048 x 2048], Kd=64
    gemm_nt<<<dim3(NKEY / 64, NKEY / 64, BB), 256>>>(
        Q, K, E, NKEY, RR, NKEY,
        (long)NKEY * RR, (long)NKEY * RR, (long)NKEY * NKEY);

    // 3) softmax over 2048 keys, fold key-depth -> A2 [B*2048, 256]
    softmax_fold<<<BB * NKEY, 256>>>(E, A2);

    // 4) attn: per (b,d) slice, [256,256] @ [256,512]
    gemm_nn<<<dim3(CC / 64, FF / 64, BB * DD), 256>>>(
        A2, V, nullptr, ATT, FF, FF, CC,
        (long)FF * FF, (long)FF * CC, (long)FF * CC);

    // 5) y1 = LN(attn + x)
    add_ln<<<MTOT, 128>>>(ATT, x, g1, b1, Y1, 0);

    // 6) MLP: T = y1 @ wm + bm
    gemm_nn<<<dim3(CC / 64, MTOT / 64, 1), 256>>>(Y1, wm, bm, T, MTOT, CC, CC, 0, 0, 0);

    // 7) out = LN(y1 + relu(T))
    add_ln<<<MTOT, 128>>>(Y1, T, g2, b2, out, 1);
}

// round 4
// speedup vs baseline: 1.0172x; 1.0172x over previous
#include <cuda_runtime.h>
#include <math.h>

// Problem constants
#define BB 4
#define DD 8
#define FF 256
#define CC 512
#define RR 64
#define NKEY 2048            // D*F
#define MTOT 8192            // B*D*F
#define LN_EPS 1e-3f

// ---------------- scratch (static device memory; no allocations) ----------------
__device__ float g_Q  [BB * NKEY * RR];          // 2 MB
__device__ float g_K  [BB * NKEY * RR];          // 2 MB
__device__ float g_V  [BB * NKEY * CC];          // 16.8 MB
__device__ float g_E  [(long)BB * NKEY * NKEY];  // 67 MB
__device__ float g_A2 [BB * NKEY * FF];          // 8.4 MB
__device__ float g_ATT[BB * NKEY * CC];          // 16.8 MB
__device__ float g_Y1 [BB * NKEY * CC];          // 16.8 MB
__device__ float g_T  [BB * NKEY * CC];          // 16.8 MB

// ---------------------------------------------------------------------------
// Tiled GEMM, BM=128, BK=8, TM=8, 256 threads, double-buffered smem.
//   BN=128, TN=8  -> 8x8 register tile (big GEMMs)
//   BN=64,  TN=4  -> 8x4 register tile (Q/K projections, N=64)
// NT=true: B is [N,K] row-major (scores E = Q @ K^T).
// All dims assumed divisible by tile sizes (true for this problem).
// ---------------------------------------------------------------------------
template<int BN, int TN, bool NT, bool BIAS>
__global__ __launch_bounds__(256, 2)
void gemm_t(const float* __restrict__ A, const float* __restrict__ B,
            const float* __restrict__ bias, float* __restrict__ C,
            int M, int K, int N, long sA, long sB, long sC)
{
    constexpr int BM = 128, BK = 8, TM = 8;
    constexpr int AP = BM + 4;   // padded strides (avoid bank conflicts on
    constexpr int BP = BN + 4;   // transpose scatter-stores)

    A += (long)blockIdx.z * sA;
    B += (long)blockIdx.z * sB;
    C += (long)blockIdx.z * sC;

    __shared__ float As[2][BK][AP];
    __shared__ float Bs[2][BK][BP];

    const int tid = threadIdx.x;           // 0..255
    const int tx  = tid & 15;              // BN/TN == 16 for both configs
    const int ty  = tid >> 4;
    const int rowBase = blockIdx.y * BM;
    const int colBase = blockIdx.x * BN;

    // A tile: 128 rows x 8 k, float4 along k, store transposed
    const int aRow = tid >> 1;             // 0..127
    const int aCol = (tid & 1) << 2;       // 0 or 4

    float acc[TM][TN] = {};

    auto loadTile = [&](int k0, int buf) {
        float4 av = *(const float4*)(A + (long)(rowBase + aRow) * K + k0 + aCol);
        As[buf][aCol + 0][aRow] = av.x;
        As[buf][aCol + 1][aRow] = av.y;
        As[buf][aCol + 2][aRow] = av.z;
        As[buf][aCol + 3][aRow] = av.w;
        if constexpr (NT) {
            // B[N,K] row-major: tile BN(=128) x BK, transpose into Bs[k][n]
            const int bRow = tid >> 1;          // 0..127
            const int bCol = (tid & 1) << 2;    // 0 or 4
            float4 bv = *(const float4*)(B + (long)(colBase + bRow) * K + k0 + bCol);
            Bs[buf][bCol + 0][bRow] = bv.x;
            Bs[buf][bCol + 1][bRow] = bv.y;
            Bs[buf][bCol + 2][bRow] = bv.z;
            Bs[buf][bCol + 3][bRow] = bv.w;
        } else if constexpr (BN == 128) {
            const int bRow = tid >> 5;          // 0..7
            const int bCol = (tid & 31) << 2;   // 0..124
            *(float4*)&Bs[buf][bRow][bCol] =
                *(const float4*)(B + (long)(k0 + bRow) * N + colBase + bCol);
        } else {                                 // BN == 64
            const int bRow = tid >> 5;          // 0..7
            const int bCol = (tid & 31) << 1;   // 0..62
            float2 bv = *(const float2*)(B + (long)(k0 + bRow) * N + colBase + bCol);
            Bs[buf][bRow][bCol]     = bv.x;
            Bs[buf][bRow][bCol + 1] = bv.y;
        }
    };

    const int nTiles = K / BK;
    loadTile(0, 0);
    __syncthreads();

    int buf = 0;
    for (int kt = 0; kt < nTiles; kt++) {
        if (kt + 1 < nTiles) loadTile((kt + 1) * BK, buf ^ 1);

#pragma unroll
        for (int kk = 0; kk < BK; kk++) {
            float a_frag[TM], b_frag[TN];
            *(float4*)&a_frag[0] = *(const float4*)&As[buf][kk][ty * TM];
            *(float4*)&a_frag[4] = *(const float4*)&As[buf][kk][ty * TM + 4];
            *(float4*)&b_frag[0] = *(const float4*)&Bs[buf][kk][tx * TN];
            if constexpr (TN == 8)
                *(float4*)&b_frag[4] = *(const float4*)&Bs[buf][kk][tx * TN + 4];
#pragma unroll
            for (int i = 0; i < TM; i++)
#pragma unroll
                for (int j = 0; j < TN; j++)
                    acc[i][j] = fmaf(a_frag[i], b_frag[j], acc[i][j]);
        }
        __syncthreads();
        buf ^= 1;
    }

    // epilogue
    float bfrag[TN];
#pragma unroll
    for (int j = 0; j < TN; j++) bfrag[j] = 0.f;
    if constexpr (BIAS) {
        *(float4*)&bfrag[0] = *(const float4*)(bias + colBase + tx * TN);
        if constexpr (TN == 8)
            *(float4*)&bfrag[4] = *(const float4*)(bias + colBase + tx * TN + 4);
    }
#pragma unroll
    for (int i = 0; i < TM; i++) {
        const long row = rowBase + ty * TM + i;
        float* cp = C + row * N + colBase + tx * TN;
        float4 o0;
        o0.x = acc[i][0] + bfrag[0];
        o0.y = acc[i][1] + bfrag[1];
        o0.z = acc[i][2] + bfrag[2];
        o0.w = acc[i][3] + bfrag[3];
        *(float4*)cp = o0;
        if constexpr (TN == 8) {
            float4 o1;
            o1.x = acc[i][4] + bfrag[4];
            o1.y = acc[i][5] + bfrag[5];
            o1.z = acc[i][6] + bfrag[6];
            o1.w = acc[i][7] + bfrag[7];
            *(float4*)(cp + 4) = o1;
        }
    }
}

// ---------------------------------------------------------------------------
// Softmax over 2048 keys + fold over key-depth g:
//   a2[row, jf] = sum_g exp(e[row, g*256+jf] - m) / Z
// One block (256 threads) per query row; thread t owns jf = t across all g.
// ---------------------------------------------------------------------------
__global__ void softmax_fold(const float* __restrict__ E, float* __restrict__ A2)
{
    const long row = blockIdx.x;
    const float* e = E + row * (long)NKEY;
    const int t = threadIdx.x;

    float v[DD];
    float m = -INFINITY;
#pragma unroll
    for (int g = 0; g < DD; g++) {
        v[g] = e[g * FF + t];
        m = fmaxf(m, v[g]);
    }

    __shared__ float red[256];
    red[t] = m;
    __syncthreads();
#pragma unroll
    for (int s = 128; s > 0; s >>= 1) {
        if (t < s) red[t] = fmaxf(red[t], red[t + s]);
        __syncthreads();
    }
    m = red[0];
    __syncthreads();

    float a = 0.f;
#pragma unroll
    for (int g = 0; g < DD; g++)
        a += __expf(v[g] - m);

    red[t] = a;
    __syncthreads();
#pragma unroll
    for (int s = 128; s > 0; s >>= 1) {
        if (t < s) red[t] += red[t + s];
        __syncthreads();
    }
    const float Z = red[0];

    A2[row * (long)FF + t] = a / Z;
}

// ---------------------------------------------------------------------------
// out_row = LayerNorm(A_row + f(B_row)) * gamma + beta, f = relu if relu_b.
// One block (128 threads, float4 each) per row of 512 channels.
// ---------------------------------------------------------------------------
__global__ void add_ln(const float* __restrict__ A, const float* __restrict__ B,
                       const float* __restrict__ gamma, const float* __restrict__ beta,
                       float* __restrict__ out, int relu_b)
{
    const long row = blockIdx.x;
    const int t = threadIdx.x;  // 0..127

    float4 a4 = ((const float4*)(A + row * CC))[t];
    float4 b4 = ((const float4*)(B + row * CC))[t];
    if (relu_b) {
        b4.x = fmaxf(b4.x, 0.f);
        b4.y = fmaxf(b4.y, 0.f);
        b4.z = fmaxf(b4.z, 0.f);
        b4.w = fmaxf(b4.w, 0.f);
    }
    float x0 = a4.x + b4.x, x1 = a4.y + b4.y, x2 = a4.z + b4.z, x3 = a4.w + b4.w;

    float s  = x0 + x1 + x2 + x3;
    float sq = x0 * x0 + x1 * x1 + x2 * x2 + x3 * x3;
#pragma unroll
    for (int o = 16; o > 0; o >>= 1) {
        s  += __shfl_xor_sync(0xFFFFFFFFu, s,  o);
        sq += __shfl_xor_sync(0xFFFFFFFFu, sq, o);
    }
    __shared__ float ss[4], qq[4];
    const int w = t >> 5, l = t & 31;
    if (l == 0) { ss[w] = s; qq[w] = sq; }
    __syncthreads();
    s  = ss[0] + ss[1] + ss[2] + ss[3];
    sq = qq[0] + qq[1] + qq[2] + qq[3];

    const float mean = s * (1.f / CC);
    const float var  = sq * (1.f / CC) - mean * mean;
    const float r    = rsqrtf(var + LN_EPS);

    float4 g4  = ((const float4*)gamma)[t];
    float4 be4 = ((const float4*)beta)[t];
    float4 o4;
    o4.x = (x0 - mean) * r * g4.x + be4.x;
    o4.y = (x1 - mean) * r * g4.y + be4.y;
    o4.z = (x2 - mean) * r * g4.z + be4.z;
    o4.w = (x3 - mean) * r * g4.w + be4.w;
    ((float4*)(out + row * CC))[t] = o4;
}

// ---------------------------------------------------------------------------
extern "C" void kernel_launch(void* const* d_in, const int* in_sizes, int n_in,
                              void* d_out, int out_size)
{
    const float* x  = (const float*)d_in[0];
    const float* wq = (const float*)d_in[1];
    const float* bq = (const float*)d_in[2];
    const float* wk = (const float*)d_in[3];
    const float* bk = (const float*)d_in[4];
    const float* wv = (const float*)d_in[5];
    const float* bv = (const float*)d_in[6];
    const float* wm = (const float*)d_in[7];
    const float* bm = (const float*)d_in[8];
    const float* g1 = (const float*)d_in[9];
    const float* b1 = (const float*)d_in[10];
    const float* g2 = (const float*)d_in[11];
    const float* b2 = (const float*)d_in[12];
    float* out = (float*)d_out;

    float *Q, *K, *V, *E, *A2, *ATT, *Y1, *T;
    cudaGetSymbolAddress((void**)&Q,   g_Q);
    cudaGetSymbolAddress((void**)&K,   g_K);
    cudaGetSymbolAddress((void**)&V,   g_V);
    cudaGetSymbolAddress((void**)&E,   g_E);
    cudaGetSymbolAddress((void**)&A2,  g_A2);
    cudaGetSymbolAddress((void**)&ATT, g_ATT);
    cudaGetSymbolAddress((void**)&Y1,  g_Y1);
    cudaGetSymbolAddress((void**)&T,   g_T);

    // 1) Q/K/V projections: [8192,512] @ [512,{64,64,512}]
    gemm_t<64, 4, false, true><<<dim3(1, MTOT / 128, 1), 256>>>(
        x, wq, bq, Q, MTOT, CC, RR, 0, 0, 0);
    gemm_t<64, 4, false, true><<<dim3(1, MTOT / 128, 1), 256>>>(
        x, wk, bk, K, MTOT, CC, RR, 0, 0, 0);
    gemm_t<128, 8, false, true><<<dim3(CC / 128, MTOT / 128, 1), 256>>>(
        x, wv, bv, V, MTOT, CC, CC, 0, 0, 0);

    // 2) scores: per batch E = Q @ K^T  [2048 x 2048], Kd=64
    gemm_t<128, 8, true, false><<<dim3(NKEY / 128, NKEY / 128, BB), 256>>>(
        Q, K, nullptr, E, NKEY, RR, NKEY,
        (long)NKEY * RR, (long)NKEY * RR, (long)NKEY * NKEY);

    // 3) softmax over 2048 keys, fold key-depth -> A2 [B*2048, 256]
    softmax_fold<<<BB * NKEY, 256>>>(E, A2);

    // 4) attn: per (b,d) slice, [256,256] @ [256,512]
    gemm_t<128, 8, false, false><<<dim3(CC / 128, FF / 128, BB * DD), 256>>>(
        A2, V, nullptr, ATT, FF, FF, CC,
        (long)FF * FF, (long)FF * CC, (long)FF * CC);

    // 5) y1 = LN(attn + x)
    add_ln<<<MTOT, 128>>>(ATT, x, g1, b1, Y1, 0);

    // 6) MLP: T = y1 @ wm + bm
    gemm_t<128, 8, false, true><<<dim3(CC / 128, MTOT / 128, 1), 256>>>(
        Y1, wm, bm, T, MTOT, CC, CC, 0, 0, 0);

    // 7) out = LN(y1 + relu(T))
    add_ln<<<MTOT, 128>>>(Y1, T, g2, b2, out, 1);
}

// round 5
// speedup vs baseline: 1.6871x; 1.6585x over previous
#include <cuda_runtime.h>
#include <cuda_bf16.h>
#include <math.h>

// Problem constants
#define BB 4
#define DD 8
#define FF 256
#define CC 512
#define RR 64
#define NKEY 2048            // D*F
#define MTOT 8192            // B*D*F
#define LN_EPS 1e-3f

// ---------------------------------------------------------------------------
// One big static scratch arena (no allocations allowed).
// ---------------------------------------------------------------------------
#define AL(x) (((x) + 255) & ~((size_t)255))
static const size_t OFF_E    = 0;                                        // f32 [4,2048,2048]
static const size_t OFF_ATT  = AL(OFF_E    + (size_t)BB*NKEY*NKEY*4);    // f32 [8192,512]
static const size_t OFF_Y1   = AL(OFF_ATT  + (size_t)MTOT*CC*4);
static const size_t OFF_T    = AL(OFF_Y1   + (size_t)MTOT*CC*4);
static const size_t OFF_XH   = AL(OFF_T    + (size_t)MTOT*CC*4);         // bf16 pairs below
static const size_t OFF_XL   = AL(OFF_XH   + (size_t)MTOT*CC*2);
static const size_t OFF_WQH  = AL(OFF_XL   + (size_t)MTOT*CC*2);
static const size_t OFF_WQL  = AL(OFF_WQH  + (size_t)CC*RR*2);
static const size_t OFF_WKH  = AL(OFF_WQL  + (size_t)CC*RR*2);
static const size_t OFF_WKL  = AL(OFF_WKH  + (size_t)CC*RR*2);
static const size_t OFF_WVH  = AL(OFF_WKL  + (size_t)CC*RR*2);
static const size_t OFF_WVL  = AL(OFF_WVH  + (size_t)CC*CC*2);
static const size_t OFF_WMH  = AL(OFF_WVL  + (size_t)CC*CC*2);
static const size_t OFF_WML  = AL(OFF_WMH  + (size_t)CC*CC*2);
static const size_t OFF_QH   = AL(OFF_WML  + (size_t)CC*CC*2);
static const size_t OFF_QL   = AL(OFF_QH   + (size_t)BB*NKEY*RR*2);
static const size_t OFF_KH   = AL(OFF_QL   + (size_t)BB*NKEY*RR*2);
static const size_t OFF_KL   = AL(OFF_KH   + (size_t)BB*NKEY*RR*2);
static const size_t OFF_VH   = AL(OFF_KL   + (size_t)BB*NKEY*RR*2);
static const size_t OFF_VL   = AL(OFF_VH   + (size_t)BB*NKEY*CC*2);
static const size_t OFF_A2H  = AL(OFF_VL   + (size_t)BB*NKEY*CC*2);
static const size_t OFF_A2L  = AL(OFF_A2H  + (size_t)BB*NKEY*FF*2);
static const size_t OFF_Y1H  = AL(OFF_A2L  + (size_t)BB*NKEY*FF*2);
static const size_t OFF_Y1L  = AL(OFF_Y1H  + (size_t)MTOT*CC*2);
static const size_t SCRATCH_TOTAL = AL(OFF_Y1L + (size_t)MTOT*CC*2);

__device__ unsigned char g_scratch[SCRATCH_TOTAL];

// ---------------------------------------------------------------------------
// helpers
// ---------------------------------------------------------------------------
typedef __nv_bfloat16 bf16;

__device__ __forceinline__ void split2(float v, bf16& h, bf16& l) {
    h = __float2bfloat16(v);
    l = __float2bfloat16(v - __bfloat162float(h));
}

__device__ __forceinline__ void ldsm_x4(unsigned r[4], unsigned addr) {
    asm volatile("ldmatrix.sync.aligned.m8n8.x4.shared.b16 {%0,%1,%2,%3}, [%4];"
                 : "=r"(r[0]), "=r"(r[1]), "=r"(r[2]), "=r"(r[3]) : "r"(addr));
}
__device__ __forceinline__ void ldsm_x2(unsigned r[2], unsigned addr) {
    asm volatile("ldmatrix.sync.aligned.m8n8.x2.shared.b16 {%0,%1}, [%2];"
                 : "=r"(r[0]), "=r"(r[1]) : "r"(addr));
}
__device__ __forceinline__ void ldsm_x2t(unsigned r[2], unsigned addr) {
    asm volatile("ldmatrix.sync.aligned.m8n8.x2.trans.shared.b16 {%0,%1}, [%2];"
                 : "=r"(r[0]), "=r"(r[1]) : "r"(addr));
}
__device__ __forceinline__ void mma_bf16(float c[4], const unsigned a[4], const unsigned b[2]) {
    asm volatile(
        "mma.sync.aligned.m16n8k16.row.col.f32.bf16.bf16.f32 "
        "{%0,%1,%2,%3}, {%4,%5,%6,%7}, {%8,%9}, {%0,%1,%2,%3};"
        : "+f"(c[0]), "+f"(c[1]), "+f"(c[2]), "+f"(c[3])
        : "r"(a[0]), "r"(a[1]), "r"(a[2]), "r"(a[3]), "r"(b[0]), "r"(b[1]));
}

// ---------------------------------------------------------------------------
// fp32 -> (bf16 hi, bf16 lo) conversion, float4 per thread
// ---------------------------------------------------------------------------
__global__ void conv_pair(const float* __restrict__ src,
                          bf16* __restrict__ h, bf16* __restrict__ l, int n4)
{
    int i = blockIdx.x * blockDim.x + threadIdx.x;
    if (i >= n4) return;
    float4 v = ((const float4*)src)[i];
    bf16 h0, l0, h1, l1, h2, l2, h3, l3;
    split2(v.x, h0, l0); split2(v.y, h1, l1);
    split2(v.z, h2, l2); split2(v.w, h3, l3);
    ((__nv_bfloat162*)h)[i * 2]     = __nv_bfloat162(h0, h1);
    ((__nv_bfloat162*)h)[i * 2 + 1] = __nv_bfloat162(h2, h3);
    ((__nv_bfloat162*)l)[i * 2]     = __nv_bfloat162(l0, l1);
    ((__nv_bfloat162*)l)[i * 2 + 1] = __nv_bfloat162(l2, l3);
}

// ---------------------------------------------------------------------------
// Tensor-core GEMM (bf16 split x3, fp32 accumulate).
//   C[M,N] = A[M,K] @ B[K,N]        (NT=false, B row-major [K][N])
//   C[M,N] = A[M,K] @ B[N,K]^T      (NT=true,  B row-major [N][K])
// A given as hi/lo bf16 pair. Block tile 128x64, BK=16.
// 256 threads = 8 warps (4m x 2n), warp tile 32x32 (2 m16-tiles x 4 n8-tiles).
// OUTPAIR: write bf16 hi/lo C instead of fp32.
// ---------------------------------------------------------------------------
template<bool NT, bool OUTPAIR, bool BIAS>
__global__ __launch_bounds__(256, 2)
void mma_gemm(const bf16* __restrict__ Ah, const bf16* __restrict__ Al,
              const bf16* __restrict__ Bh, const bf16* __restrict__ Bl,
              const float* __restrict__ bias,
              float* __restrict__ Cf, bf16* __restrict__ Ch, bf16* __restrict__ Cl,
              int M, int K, int N, long sA, long sB, long sC)
{
    constexpr int BM = 128, BN = 64, BK = 16;
    constexpr int AP  = BK + 8;    // 24: padded A row (also NT B row)
    constexpr int BPN = BN + 8;    // 72: padded NN B row
    constexpr int BSZ = 1536;      // max(16*72, 64*24)

    Ah += blockIdx.z * sA; Al += blockIdx.z * sA;
    Bh += blockIdx.z * sB; Bl += blockIdx.z * sB;
    if (OUTPAIR) { Ch += blockIdx.z * sC; Cl += blockIdx.z * sC; }
    else         { Cf += blockIdx.z * sC; }

    __shared__ bf16 sAh[2][BM * AP], sAl[2][BM * AP];
    __shared__ bf16 sBh[2][BSZ],     sBl[2][BSZ];

    const int tid  = threadIdx.x;
    const int lane = tid & 31;
    const int warp = tid >> 5;
    const int wm   = warp & 3;     // 0..3
    const int wn   = warp >> 2;    // 0..1
    const int rowBase = blockIdx.y * BM;
    const int colBase = blockIdx.x * BN;

    const unsigned sAh_b = (unsigned)__cvta_generic_to_shared(sAh);
    const unsigned sAl_b = (unsigned)__cvta_generic_to_shared(sAl);
    const unsigned sBh_b = (unsigned)__cvta_generic_to_shared(sBh);
    const unsigned sBl_b = (unsigned)__cvta_generic_to_shared(sBl);

    float acc[2][4][4] = {};

    // gmem staging regs
    uint4 stAh, stAl; uint2 stBh, stBl;

    const int ar = tid >> 1, ac = (tid & 1) * 8;       // A: 128 rows x 16, uint4 (8 bf16)
    auto gload = [&](int kt) {
        const int k0 = kt * BK;
        long aoff = (long)(rowBase + ar) * K + k0 + ac;
        stAh = *(const uint4*)(Ah + aoff);
        stAl = *(const uint4*)(Al + aoff);
        if constexpr (NT) {
            const int br = tid >> 2, bc = (tid & 3) * 4;   // 64 rows x 16
            long boff = (long)(colBase + br) * K + k0 + bc;
            stBh = *(const uint2*)(Bh + boff);
            stBl = *(const uint2*)(Bl + boff);
        } else {
            const int br = tid >> 4, bc = (tid & 15) * 4;  // 16 rows x 64
            long boff = (long)(k0 + br) * N + colBase + bc;
            stBh = *(const uint2*)(Bh + boff);
            stBl = *(const uint2*)(Bl + boff);
        }
    };
    auto gstore = [&](int buf) {
        *(uint4*)&sAh[buf][ar * AP + ac] = stAh;
        *(uint4*)&sAl[buf][ar * AP + ac] = stAl;
        if constexpr (NT) {
            const int br = tid >> 2, bc = (tid & 3) * 4;
            *(uint2*)&sBh[buf][br * AP + bc] = stBh;
            *(uint2*)&sBl[buf][br * AP + bc] = stBl;
        } else {
            const int br = tid >> 4, bc = (tid & 15) * 4;
            *(uint2*)&sBh[buf][br * BPN + bc] = stBh;
            *(uint2*)&sBl[buf][br * BPN + bc] = stBl;
        }
    };

    auto compute = [&](int buf) {
        unsigned afh[2][4], afl[2][4], bfh[4][2], bfl[4][2];
#pragma unroll
        for (int mi = 0; mi < 2; mi++) {
            unsigned idx = (unsigned)((wm * 32 + mi * 16 + (lane & 15)) * AP + 8 * (lane >> 4));
            ldsm_x4(afh[mi], sAh_b + (buf * (BM * AP) + idx) * 2u);
            ldsm_x4(afl[mi], sAl_b + (buf * (BM * AP) + idx) * 2u);
        }
#pragma unroll
        for (int ni = 0; ni < 4; ni++) {
            if constexpr (NT) {
                unsigned idx = (unsigned)((wn * 32 + ni * 8 + (lane & 7)) * AP + 8 * ((lane >> 3) & 1));
                ldsm_x2(bfh[ni], sBh_b + (buf * BSZ + idx) * 2u);
                ldsm_x2(bfl[ni], sBl_b + (buf * BSZ + idx) * 2u);
            } else {
                unsigned idx = (unsigned)((lane & 15) * BPN + wn * 32 + ni * 8);
                ldsm_x2t(bfh[ni], sBh_b + (buf * BSZ + idx) * 2u);
                ldsm_x2t(bfl[ni], sBl_b + (buf * BSZ + idx) * 2u);
            }
        }
#pragma unroll
        for (int mi = 0; mi < 2; mi++)
#pragma unroll
            for (int ni = 0; ni < 4; ni++) {
                mma_bf16(acc[mi][ni], afh[mi], bfh[ni]);   // hi*hi
                mma_bf16(acc[mi][ni], afh[mi], bfl[ni]);   // hi*lo
                mma_bf16(acc[mi][ni], afl[mi], bfh[ni]);   // lo*hi
            }
    };

    const int nT = K / BK;
    gload(0); gstore(0);
    __syncthreads();
    int buf = 0;
    for (int kt = 0; kt < nT; kt++) {
        const bool more = (kt + 1 < nT);
        if (more) gload(kt + 1);
        compute(buf);
        if (more) gstore(buf ^ 1);
        __syncthreads();
        buf ^= 1;
    }

    // epilogue
    const int g = lane >> 2, t = lane & 3;
#pragma unroll
    for (int ni = 0; ni < 4; ni++) {
        const int c = colBase + wn * 32 + ni * 8 + 2 * t;
        float bx = 0.f, by = 0.f;
        if constexpr (BIAS) { bx = bias[c]; by = bias[c + 1]; }
#pragma unroll
        for (int mi = 0; mi < 2; mi++) {
            const int r0 = rowBase + wm * 32 + mi * 16 + g;
            const float v00 = acc[mi][ni][0] + bx, v01 = acc[mi][ni][1] + by;
            const float v10 = acc[mi][ni][2] + bx, v11 = acc[mi][ni][3] + by;
            if constexpr (OUTPAIR) {
                bf16 h0, l0, h1, l1;
                split2(v00, h0, l0); split2(v01, h1, l1);
                *(__nv_bfloat162*)(Ch + (long)r0 * N + c) = __nv_bfloat162(h0, h1);
                *(__nv_bfloat162*)(Cl + (long)r0 * N + c) = __nv_bfloat162(l0, l1);
                split2(v10, h0, l0); split2(v11, h1, l1);
                *(__nv_bfloat162*)(Ch + (long)(r0 + 8) * N + c) = __nv_bfloat162(h0, h1);
                *(__nv_bfloat162*)(Cl + (long)(r0 + 8) * N + c) = __nv_bfloat162(l0, l1);
            } else {
                *(float2*)(Cf + (long)r0 * N + c)       = make_float2(v00, v01);
                *(float2*)(Cf + (long)(r0 + 8) * N + c) = make_float2(v10, v11);
            }
        }
    }
}

// ---------------------------------------------------------------------------
// Softmax over 2048 keys + fold over key-depth g; writes bf16 hi/lo A2.
// One block (256 threads) per query row.
// ---------------------------------------------------------------------------
__global__ void softmax_fold(const float* __restrict__ E,
                             bf16* __restrict__ A2h, bf16* __restrict__ A2l)
{
    const long row = blockIdx.x;
    const float* e = E + row * (long)NKEY;
    const int t = threadIdx.x;

    float v[DD];
    float m = -INFINITY;
#pragma unroll
    for (int g = 0; g < DD; g++) {
        v[g] = e[g * FF + t];
        m = fmaxf(m, v[g]);
    }

    __shared__ float red[256];
    red[t] = m;
    __syncthreads();
#pragma unroll
    for (int s = 128; s > 0; s >>= 1) {
        if (t < s) red[t] = fmaxf(red[t], red[t + s]);
        __syncthreads();
    }
    m = red[0];
    __syncthreads();

    float a = 0.f;
#pragma unroll
    for (int g = 0; g < DD; g++)
        a += __expf(v[g] - m);

    red[t] = a;
    __syncthreads();
#pragma unroll
    for (int s = 128; s > 0; s >>= 1) {
        if (t < s) red[t] += red[t + s];
        __syncthreads();
    }
    const float Z = red[0];

    bf16 h, l;
    split2(a / Z, h, l);
    A2h[row * (long)FF + t] = h;
    A2l[row * (long)FF + t] = l;
}

// ---------------------------------------------------------------------------
// out = LayerNorm(A + f(B)) * gamma + beta; f=relu if relu_b.
// Optionally also emits bf16 hi/lo of the result (for downstream GEMM).
// ---------------------------------------------------------------------------
__global__ void add_ln(const float* __restrict__ A, const float* __restrict__ B,
                       const float* __restrict__ gamma, const float* __restrict__ beta,
                       float* __restrict__ outF,
                       bf16* __restrict__ outH, bf16* __restrict__ outL,
                       int relu_b)
{
    const long row = blockIdx.x;
    const int t = threadIdx.x;  // 0..127

    float4 a4 = ((const float4*)(A + row * CC))[t];
    float4 b4 = ((const float4*)(B + row * CC))[t];
    if (relu_b) {
        b4.x = fmaxf(b4.x, 0.f);
        b4.y = fmaxf(b4.y, 0.f);
        b4.z = fmaxf(b4.z, 0.f);
        b4.w = fmaxf(b4.w, 0.f);
    }
    float x0 = a4.x + b4.x, x1 = a4.y + b4.y, x2 = a4.z + b4.z, x3 = a4.w + b4.w;

    float s  = x0 + x1 + x2 + x3;
    float sq = x0 * x0 + x1 * x1 + x2 * x2 + x3 * x3;
#pragma unroll
    for (int o = 16; o > 0; o >>= 1) {
        s  += __shfl_xor_sync(0xFFFFFFFFu, s,  o);
        sq += __shfl_xor_sync(0xFFFFFFFFu, sq, o);
    }
    __shared__ float ss[4], qq[4];
    const int w = t >> 5, l = t & 31;
    if (l == 0) { ss[w] = s; qq[w] = sq; }
    __syncthreads();
    s  = ss[0] + ss[1] + ss[2] + ss[3];
    sq = qq[0] + qq[1] + qq[2] + qq[3];

    const float mean = s * (1.f / CC);
    const float var  = sq * (1.f / CC) - mean * mean;
    const float r    = rsqrtf(var + LN_EPS);

    float4 g4  = ((const float4*)gamma)[t];
    float4 be4 = ((const float4*)beta)[t];
    float4 o4;
    o4.x = (x0 - mean) * r * g4.x + be4.x;
    o4.y = (x1 - mean) * r * g4.y + be4.y;
    o4.z = (x2 - mean) * r * g4.z + be4.z;
    o4.w = (x3 - mean) * r * g4.w + be4.w;
    ((float4*)(outF + row * CC))[t] = o4;

    if (outH) {
        bf16 h0, l0, h1, l1, h2, l2, h3, l3;
        split2(o4.x, h0, l0); split2(o4.y, h1, l1);
        split2(o4.z, h2, l2); split2(o4.w, h3, l3);
        long i = row * (CC / 2) + t * 2;
        ((__nv_bfloat162*)outH)[i]     = __nv_bfloat162(h0, h1);
        ((__nv_bfloat162*)outH)[i + 1] = __nv_bfloat162(h2, h3);
        ((__nv_bfloat162*)outL)[i]     = __nv_bfloat162(l0, l1);
        ((__nv_bfloat162*)outL)[i + 1] = __nv_bfloat162(l2, l3);
    }
}

// ---------------------------------------------------------------------------
extern "C" void kernel_launch(void* const* d_in, const int* in_sizes, int n_in,
                              void* d_out, int out_size)
{
    const float* x  = (const float*)d_in[0];
    const float* wq = (const float*)d_in[1];
    const float* bq = (const float*)d_in[2];
    const float* wk = (const float*)d_in[3];
    const float* bk = (const float*)d_in[4];
    const float* wv = (const float*)d_in[5];
    const float* bv = (const float*)d_in[6];
    const float* wm = (const float*)d_in[7];
    const float* bm = (const float*)d_in[8];
    const float* g1 = (const float*)d_in[9];
    const float* b1 = (const float*)d_in[10];
    const float* g2 = (const float*)d_in[11];
    const float* b2 = (const float*)d_in[12];
    float* out = (float*)d_out;

    unsigned char* base;
    cudaGetSymbolAddress((void**)&base, g_scratch);

    float* E   = (float*)(base + OFF_E);
    float* ATT = (float*)(base + OFF_ATT);
    float* Y1  = (float*)(base + OFF_Y1);
    float* T   = (float*)(base + OFF_T);
    bf16 *xh  = (bf16*)(base + OFF_XH),  *xl  = (bf16*)(base + OFF_XL);
    bf16 *wqh = (bf16*)(base + OFF_WQH), *wql = (bf16*)(base + OFF_WQL);
    bf16 *wkh = (bf16*)(base + OFF_WKH), *wkl = (bf16*)(base + OFF_WKL);
    bf16 *wvh = (bf16*)(base + OFF_WVH), *wvl = (bf16*)(base + OFF_WVL);
    bf16 *wmh = (bf16*)(base + OFF_WMH), *wml = (bf16*)(base + OFF_WML);
    bf16 *Qh  = (bf16*)(base + OFF_QH),  *Ql  = (bf16*)(base + OFF_QL);
    bf16 *Kh  = (bf16*)(base + OFF_KH),  *Kl  = (bf16*)(base + OFF_KL);
    bf16 *Vh  = (bf16*)(base + OFF_VH),  *Vl  = (bf16*)(base + OFF_VL);
    bf16 *A2h = (bf16*)(base + OFF_A2H), *A2l = (bf16*)(base + OFF_A2L);
    bf16 *Y1h = (bf16*)(base + OFF_Y1H), *Y1l = (bf16*)(base + OFF_Y1L);

    // 0) conversions to bf16 hi/lo
    conv_pair<<<(MTOT * CC / 4 + 255) / 256, 256>>>(x,  xh,  xl,  MTOT * CC / 4);
    conv_pair<<<(CC * RR / 4 + 255) / 256, 256>>>(wq, wqh, wql, CC * RR / 4);
    conv_pair<<<(CC * RR / 4 + 255) / 256, 256>>>(wk, wkh, wkl, CC * RR / 4);
    conv_pair<<<(CC * CC / 4 + 255) / 256, 256>>>(wv, wvh, wvl, CC * CC / 4);
    conv_pair<<<(CC * CC / 4 + 255) / 256, 256>>>(wm, wmh, wml, CC * CC / 4);

    // 1) Q/K/V projections (outputs bf16 pair)
    mma_gemm<false, true, true><<<dim3(1, MTOT / 128, 1), 256>>>(
        xh, xl, wqh, wql, bq, nullptr, Qh, Ql, MTOT, CC, RR, 0, 0, 0);
    mma_gemm<false, true, true><<<dim3(1, MTOT / 128, 1), 256>>>(
        xh, xl, wkh, wkl, bk, nullptr, Kh, Kl, MTOT, CC, RR, 0, 0, 0);
    mma_gemm<false, true, true><<<dim3(CC / 64, MTOT / 128, 1), 256>>>(
        xh, xl, wvh, wvl, bv, nullptr, Vh, Vl, MTOT, CC, CC, 0, 0, 0);

    // 2) scores: per batch E = Q @ K^T
    mma_gemm<true, false, false><<<dim3(NKEY / 64, NKEY / 128, BB), 256>>>(
        Qh, Ql, Kh, Kl, nullptr, E, nullptr, nullptr,
        NKEY, RR, NKEY, (long)NKEY * RR, (long)NKEY * RR, (long)NKEY * NKEY);

    // 3) softmax over 2048 keys + key-depth fold -> A2 (bf16 pair)
    softmax_fold<<<BB * NKEY, 256>>>(E, A2h, A2l);

    // 4) attn: per (b,d) slice, [256,256] @ [256,512]
    mma_gemm<false, false, false><<<dim3(CC / 64, FF / 128, BB * DD), 256>>>(
        A2h, A2l, Vh, Vl, nullptr, ATT, nullptr, nullptr,
        FF, FF, CC, (long)FF * FF, (long)FF * CC, (long)FF * CC);

    // 5) y1 = LN(attn + x), also emit bf16 pair
    add_ln<<<MTOT, 128>>>(ATT, x, g1, b1, Y1, Y1h, Y1l, 0);

    // 6) MLP: T = y1 @ wm + bm
    mma_gemm<false, false, true><<<dim3(CC / 64, MTOT / 128, 1), 256>>>(
        Y1h, Y1l, wmh, wml, bm, T, nullptr, nullptr, MTOT, CC, CC, 0, 0, 0);

    // 7) out = LN(y1 + relu(T))
    add_ln<<<MTOT, 128>>>(Y1, T, g2, b2, out, nullptr, nullptr, 1);
}

// round 12
// speedup vs baseline: 2.1575x; 1.2788x over previous
#include <cuda_runtime.h>
#include <cuda_bf16.h>
#include <stdint.h>
#include <cstdint>
#include <math.h>

// Problem constants
#define BB 4
#define DD 8
#define FF 256
#define CC 512
#define RR 64
#define NKEY 2048            // D*F
#define MTOT 8192            // B*D*F
#define LN_EPS 1e-3f

typedef __nv_bfloat16 bf16;

// ---------------------------------------------------------------------------
// Scratch arena (static device memory; no allocations).
// ---------------------------------------------------------------------------
#define AL(x) (((x) + 255) & ~((size_t)255))
static const size_t OFF_E     = 0;                                        // f32 [4,2048,2048]
static const size_t OFF_ATT   = AL(OFF_E     + (size_t)BB*NKEY*NKEY*4);
static const size_t OFF_Y1    = AL(OFF_ATT   + (size_t)MTOT*CC*4);
static const size_t OFF_T     = AL(OFF_Y1    + (size_t)MTOT*CC*4);
static const size_t OFF_XH    = AL(OFF_T     + (size_t)MTOT*CC*4);
static const size_t OFF_XL    = AL(OFF_XH    + (size_t)MTOT*CC*2);
static const size_t OFF_WQKH  = AL(OFF_XL    + (size_t)MTOT*CC*2);        // [128,512] w^T
static const size_t OFF_WQKL  = AL(OFF_WQKH  + (size_t)128*CC*2);
static const size_t OFF_WVH   = AL(OFF_WQKL  + (size_t)128*CC*2);         // [512,512] w^T
static const size_t OFF_WVL   = AL(OFF_WVH   + (size_t)CC*CC*2);
static const size_t OFF_WMH   = AL(OFF_WVL   + (size_t)CC*CC*2);
static const size_t OFF_WML   = AL(OFF_WMH   + (size_t)CC*CC*2);
static const size_t OFF_QKH   = AL(OFF_WML   + (size_t)CC*CC*2);          // [8192,128]
static const size_t OFF_QKL   = AL(OFF_QKH   + (size_t)MTOT*128*2);
static const size_t OFF_VH    = AL(OFF_QKL   + (size_t)MTOT*128*2);       // [8192,512]
static const size_t OFF_VL    = AL(OFF_VH    + (size_t)MTOT*CC*2);
static const size_t OFF_A2H   = AL(OFF_VL    + (size_t)MTOT*CC*2);
static const size_t OFF_A2L   = AL(OFF_A2H   + (size_t)BB*NKEY*FF*2);
static const size_t OFF_Y1H   = AL(OFF_A2L   + (size_t)BB*NKEY*FF*2);
static const size_t OFF_Y1L   = AL(OFF_Y1H   + (size_t)MTOT*CC*2);
static const size_t OFF_BQK   = AL(OFF_Y1L   + (size_t)MTOT*CC*2);        // f32 [128]
static const size_t SCRATCH_TOTAL = AL(OFF_BQK + 128*4);

__device__ unsigned char g_scratch[SCRATCH_TOTAL];

// ---------------------------------------------------------------------------
// helpers
// ---------------------------------------------------------------------------
__device__ __forceinline__ uint32_t smem_u32(const void* p) {
    uint32_t a;
    asm("{ .reg .u64 t; cvta.to.shared.u64 t, %1; cvt.u32.u64 %0, t; }" : "=r"(a) : "l"(p));
    return a;
}
__device__ __forceinline__ void split2(float v, bf16& h, bf16& l) {
    h = __float2bfloat16(v);
    l = __float2bfloat16(v - __bfloat162float(h));
}
__device__ __forceinline__ unsigned pack2(bf16 a, bf16 b) {
    __nv_bfloat162 t(a, b);
    return *(unsigned*)&t;
}
__device__ __forceinline__ void ldsm_x4(unsigned r[4], uint32_t addr) {
    asm volatile("ldmatrix.sync.aligned.m8n8.x4.shared.b16 {%0,%1,%2,%3}, [%4];"
                 : "=r"(r[0]), "=r"(r[1]), "=r"(r[2]), "=r"(r[3]) : "r"(addr));
}
__device__ __forceinline__ void ldsm_x4t(unsigned r[4], uint32_t addr) {
    asm volatile("ldmatrix.sync.aligned.m8n8.x4.trans.shared.b16 {%0,%1,%2,%3}, [%4];"
                 : "=r"(r[0]), "=r"(r[1]), "=r"(r[2]), "=r"(r[3]) : "r"(addr));
}
__device__ __forceinline__ void mma_bf16(float c[4], const unsigned a[4], const unsigned b[2]) {
    asm volatile(
        "mma.sync.aligned.m16n8k16.row.col.f32.bf16.bf16.f32 "
        "{%0,%1,%2,%3}, {%4,%5,%6,%7}, {%8,%9}, {%0,%1,%2,%3};"
        : "+f"(c[0]), "+f"(c[1]), "+f"(c[2]), "+f"(c[3])
        : "r"(a[0]), "r"(a[1]), "r"(a[2]), "r"(a[3]), "r"(b[0]), "r"(b[1]));
}
__device__ __forceinline__ void cpa(uint32_t dst, const void* src) {
    asm volatile(
        "{ .reg .u64 g; cvta.to.global.u64 g, %1; cp.async.cg.shared.global [%0], [g], 16; }"
        :: "r"(dst), "l"(src) : "memory");
}
__device__ __forceinline__ void cp_commit() {
    asm volatile("cp.async.commit_group;" ::: "memory");
}
template<int N>
__device__ __forceinline__ void cp_wait() {
    asm volatile("cp.async.wait_group %0;" :: "n"(N) : "memory");
}

// ---------------------------------------------------------------------------
// HMMA GEMM, split-bf16 x3, fp32 accumulate, cp.async 3-stage pipeline.
//   NN=false: C[M,N] = A[M,K] @ B[N,K]^T   (B K-major)
//   NN=true : C[M,N] = A[M,K] @ B[K,N]     (B N-major, ldsm trans)
// Block tile 128x64, BK=32, 8 warps (4m x 2n), warp tile 32x32.
// OUTMODE: 0 = fp32 out, 1 = bf16 hi/lo pair out.
// ---------------------------------------------------------------------------
#define STAGE_BYTES 30720       // Ah 10240 + Al 10240 + B 10240(max)
#define NSTAGE 3
#define GEMM_DSMEM (NSTAGE * STAGE_BYTES + 128)

template<bool NN, int OUTMODE, bool BIAS>
__global__ __launch_bounds__(256, 2)
void hgemm(const bf16* __restrict__ Ah, const bf16* __restrict__ Al, int lda, long sA,
           const bf16* __restrict__ Bh, const bf16* __restrict__ Bl, int ldb, long sB,
           const float* __restrict__ bias,
           float* __restrict__ Cf, bf16* __restrict__ Ch, bf16* __restrict__ Cl,
           int ldc, long sC, int Kdim)
{
    extern __shared__ __align__(128) char dyn[];
    const int z = blockIdx.z;
    Ah += z * sA; Al += z * sA;
    Bh += z * sB; Bl += z * sB;
    if (OUTMODE == 0) Cf += z * sC;
    else { Ch += z * sC; Cl += z * sC; }

    const int tid  = threadIdx.x;
    const int lane = tid & 31;
    const int warp = tid >> 5;
    const int wm   = warp & 3;      // 0..3, m-quadrant
    const int wn   = warp >> 2;     // 0..1, n-half
    const int rowBase = blockIdx.y * 128;
    const int colBase = blockIdx.x * 64;

    uint32_t sb = smem_u32(dyn);
    sb = (sb + 127) & ~127u;

    float acc[2][4][4] = {};

    // A: 128 rows x 32 bf16, pitch 40 (80B) -> conflict-free ldsm
    // B NT: 64 rows x 32, pitch 40;  B NN: 32 rows x 64, pitch 72 (144B)
    auto load = [&](int kt, int st) {
        const int k0 = kt * 32;
        const uint32_t stb = sb + st * STAGE_BYTES;
#pragma unroll
        for (int i = 0; i < 2; i++) {
            const int u = tid + i * 256;       // 0..511 16B-chunks
            const int r = u >> 2, c = u & 3;
            const uint32_t d = stb + r * 80 + c * 16;
            const long off = (long)(rowBase + r) * lda + k0 + c * 8;
            cpa(d,         Ah + off);
            cpa(d + 10240, Al + off);
        }
        if (!NN) {
            const int r = tid >> 2, c = tid & 3;     // 64 rows x 4 chunks
            const uint32_t d = stb + 20480 + r * 80 + c * 16;
            const long off = (long)(colBase + r) * ldb + k0 + c * 8;
            cpa(d,        Bh + off);
            cpa(d + 5120, Bl + off);
        } else {
            const int r = tid >> 3, c = tid & 7;     // 32 rows x 8 chunks
            const uint32_t d = stb + 20480 + r * 144 + c * 16;
            const long off = (long)(k0 + r) * ldb + colBase + c * 8;
            cpa(d,        Bh + off);
            cpa(d + 4608, Bl + off);
        }
        cp_commit();
    };

    auto compute = [&](int st) {
        const uint32_t stb = sb + st * STAGE_BYTES;
#pragma unroll
        for (int s = 0; s < 2; s++) {          // two k16 steps per chunk
            unsigned afh[2][4], afl[2][4], bh[4][2], bl[4][2];
#pragma unroll
            for (int mi = 0; mi < 2; mi++) {
                const uint32_t ad = stb + (wm * 32 + mi * 16 + (lane & 15)) * 80
                                  + s * 32 + (lane >> 4) * 16;
                ldsm_x4(afh[mi], ad);
                ldsm_x4(afl[mi], ad + 10240);
            }
#pragma unroll
            for (int pr = 0; pr < 2; pr++) {
                unsigned t[4];
                uint32_t bd;
                if (!NN) {
                    const int nrow = wn * 32 + pr * 16 + (lane & 7) + ((lane >> 4) & 1) * 8;
                    bd = stb + 20480 + nrow * 80 + s * 32 + ((lane >> 3) & 1) * 16;
                    ldsm_x4(t, bd);
                } else {
                    const int krow = s * 16 + (lane & 15);
                    bd = stb + 20480 + krow * 144
                       + (wn * 32 + pr * 16 + ((lane >> 4) & 1) * 8) * 2;
                    ldsm_x4t(t, bd);
                }
                bh[2*pr][0] = t[0]; bh[2*pr][1] = t[1];
                bh[2*pr+1][0] = t[2]; bh[2*pr+1][1] = t[3];
                if (!NN) ldsm_x4(t, bd + 5120); else ldsm_x4t(t, bd + 4608);
                bl[2*pr][0] = t[0]; bl[2*pr][1] = t[1];
                bl[2*pr+1][0] = t[2]; bl[2*pr+1][1] = t[3];
            }
#pragma unroll
            for (int mi = 0; mi < 2; mi++)
#pragma unroll
                for (int ni = 0; ni < 4; ni++) {
                    mma_bf16(acc[mi][ni], afh[mi], bh[ni]);   // hi*hi
                    mma_bf16(acc[mi][ni], afh[mi], bl[ni]);   // hi*lo
                    mma_bf16(acc[mi][ni], afl[mi], bh[ni]);   // lo*hi
                }
        }
    };

    const int nT = Kdim / 32;      // >= 2 for all our shapes
    load(0, 0);
    load(1, 1);
    if (nT > 2) load(2, 2);

    for (int kt = 0; kt < nT; kt++) {
        const int rem = nT - 1 - kt;           // groups that may stay pending
        if (rem >= 2)      cp_wait<2>();
        else if (rem == 1) cp_wait<1>();
        else               cp_wait<0>();
        __syncthreads();
        const int st = kt % NSTAGE;
        compute(st);
        __syncthreads();
        if (kt + 3 < nT) load(kt + 3, st);
    }

    // epilogue: direct global stores
    const int g = lane >> 2, t4 = lane & 3;
#pragma unroll
    for (int ni = 0; ni < 4; ni++) {
        const int c = colBase + wn * 32 + ni * 8 + 2 * t4;
        float bx = 0.f, by = 0.f;
        if (BIAS) { bx = bias[c]; by = bias[c + 1]; }
#pragma unroll
        for (int mi = 0; mi < 2; mi++) {
            const int r0 = rowBase + wm * 32 + mi * 16 + g;
            const float v00 = acc[mi][ni][0] + bx, v01 = acc[mi][ni][1] + by;
            const float v10 = acc[mi][ni][2] + bx, v11 = acc[mi][ni][3] + by;
            if (OUTMODE == 0) {
                *(float2*)(Cf + (long)r0 * ldc + c)       = make_float2(v00, v01);
                *(float2*)(Cf + (long)(r0 + 8) * ldc + c) = make_float2(v10, v11);
            } else {
                bf16 h0, l0, h1, l1;
                split2(v00, h0, l0); split2(v01, h1, l1);
                *(unsigned*)(Ch + (long)r0 * ldc + c) = pack2(h0, h1);
                *(unsigned*)(Cl + (long)r0 * ldc + c) = pack2(l0, l1);
                split2(v10, h0, l0); split2(v11, h1, l1);
                *(unsigned*)(Ch + (long)(r0 + 8) * ldc + c) = pack2(h0, h1);
                *(unsigned*)(Cl + (long)(r0 + 8) * ldc + c) = pack2(l0, l1);
            }
        }
    }
}

// ---------------------------------------------------------------------------
// fp32 -> (bf16 hi, bf16 lo), float4 per thread
// ---------------------------------------------------------------------------
__global__ void conv_pair(const float* __restrict__ src,
                          bf16* __restrict__ h, bf16* __restrict__ l, int n4)
{
    int i = blockIdx.x * blockDim.x + threadIdx.x;
    if (i >= n4) return;
    float4 v = ((const float4*)src)[i];
    bf16 h0, l0, h1, l1, h2, l2, h3, l3;
    split2(v.x, h0, l0); split2(v.y, h1, l1);
    split2(v.z, h2, l2); split2(v.w, h3, l3);
    ((__nv_bfloat162*)h)[i * 2]     = __nv_bfloat162(h0, h1);
    ((__nv_bfloat162*)h)[i * 2 + 1] = __nv_bfloat162(h2, h3);
    ((__nv_bfloat162*)l)[i * 2]     = __nv_bfloat162(l0, l1);
    ((__nv_bfloat162*)l)[i * 2 + 1] = __nv_bfloat162(l2, l3);
}

// transpose + split weights: src[K][N] -> dst[(n+rowOff)][K] hi/lo
__global__ void convw_t(const float* __restrict__ src, bf16* __restrict__ h,
                        bf16* __restrict__ l, int Krows, int Ncols, int rowOff)
{
    int i = blockIdx.x * blockDim.x + threadIdx.x;
    if (i >= Krows * Ncols) return;
    int k = i / Ncols, n = i % Ncols;
    bf16 hh, ll;
    split2(src[i], hh, ll);
    long d = (long)(n + rowOff) * Krows + k;
    h[d] = hh; l[d] = ll;
}

__global__ void packb(const float* __restrict__ a, const float* __restrict__ b,
                      float* __restrict__ d)
{
    int i = threadIdx.x;
    if (i < 64) { d[i] = a[i]; d[64 + i] = b[i]; }
}

// ---------------------------------------------------------------------------
// Softmax over 2048 keys + fold over key-depth; writes bf16 hi/lo A2.
// ---------------------------------------------------------------------------
__global__ void softmax_fold(const float* __restrict__ E,
                             bf16* __restrict__ A2h, bf16* __restrict__ A2l)
{
    const long row = blockIdx.x;
    const float* e = E + row * (long)NKEY;
    const int t = threadIdx.x;

    float v[DD];
    float m = -INFINITY;
#pragma unroll
    for (int g = 0; g < DD; g++) {
        v[g] = e[g * FF + t];
        m = fmaxf(m, v[g]);
    }

    __shared__ float red[256];
    red[t] = m;
    __syncthreads();
#pragma unroll
    for (int s = 128; s > 0; s >>= 1) {
        if (t < s) red[t] = fmaxf(red[t], red[t + s]);
        __syncthreads();
    }
    m = red[0];
    __syncthreads();

    float a = 0.f;
#pragma unroll
    for (int g = 0; g < DD; g++)
        a += __expf(v[g] - m);

    red[t] = a;
    __syncthreads();
#pragma unroll
    for (int s = 128; s > 0; s >>= 1) {
        if (t < s) red[t] += red[t + s];
        __syncthreads();
    }
    const float Z = red[0];

    bf16 h, l;
    split2(a / Z, h, l);
    A2h[row * (long)FF + t] = h;
    A2l[row * (long)FF + t] = l;
}

// ---------------------------------------------------------------------------
// out = LayerNorm(A + f(B)) * gamma + beta; f=relu if relu_b; optional bf16 pair.
// ---------------------------------------------------------------------------
__global__ void add_ln(const float* __restrict__ A, const float* __restrict__ B,
                       const float* __restrict__ gamma, const float* __restrict__ beta,
                       float* __restrict__ outF,
                       bf16* __restrict__ outH, bf16* __restrict__ outL,
                       int relu_b)
{
    const long row = blockIdx.x;
    const int t = threadIdx.x;  // 0..127

    float4 a4 = ((const float4*)(A + row * CC))[t];
    float4 b4 = ((const float4*)(B + row * CC))[t];
    if (relu_b) {
        b4.x = fmaxf(b4.x, 0.f);
        b4.y = fmaxf(b4.y, 0.f);
        b4.z = fmaxf(b4.z, 0.f);
        b4.w = fmaxf(b4.w, 0.f);
    }
    float x0 = a4.x + b4.x, x1 = a4.y + b4.y, x2 = a4.z + b4.z, x3 = a4.w + b4.w;

    float s  = x0 + x1 + x2 + x3;
    float sq = x0 * x0 + x1 * x1 + x2 * x2 + x3 * x3;
#pragma unroll
    for (int o = 16; o > 0; o >>= 1) {
        s  += __shfl_xor_sync(0xFFFFFFFFu, s,  o);
        sq += __shfl_xor_sync(0xFFFFFFFFu, sq, o);
    }
    __shared__ float ss[4], qq[4];
    const int w = t >> 5, l = t & 31;
    if (l == 0) { ss[w] = s; qq[w] = sq; }
    __syncthreads();
    s  = ss[0] + ss[1] + ss[2] + ss[3];
    sq = qq[0] + qq[1] + qq[2] + qq[3];

    const float mean = s * (1.f / CC);
    const float var  = sq * (1.f / CC) - mean * mean;
    const float r    = rsqrtf(var + LN_EPS);

    float4 g4  = ((const float4*)gamma)[t];
    float4 be4 = ((const float4*)beta)[t];
    float4 o4;
    o4.x = (x0 - mean) * r * g4.x + be4.x;
    o4.y = (x1 - mean) * r * g4.y + be4.y;
    o4.z = (x2 - mean) * r * g4.z + be4.z;
    o4.w = (x3 - mean) * r * g4.w + be4.w;
    ((float4*)(outF + row * CC))[t] = o4;

    if (outH) {
        bf16 h0, l0, h1, l1, h2, l2, h3, l3;
        split2(o4.x, h0, l0); split2(o4.y, h1, l1);
        split2(o4.z, h2, l2); split2(o4.w, h3, l3);
        long i = row * (CC / 2) + t * 2;
        ((__nv_bfloat162*)outH)[i]     = __nv_bfloat162(h0, h1);
        ((__nv_bfloat162*)outH)[i + 1] = __nv_bfloat162(h2, h3);
        ((__nv_bfloat162*)outL)[i]     = __nv_bfloat162(l0, l1);
        ((__nv_bfloat162*)outL)[i + 1] = __nv_bfloat162(l2, l3);
    }
}

// ---------------------------------------------------------------------------
extern "C" void kernel_launch(void* const* d_in, const int* in_sizes, int n_in,
                              void* d_out, int out_size)
{
    const float* x  = (const float*)d_in[0];
    const float* wq = (const float*)d_in[1];
    const float* bq = (const float*)d_in[2];
    const float* wk = (const float*)d_in[3];
    const float* bk = (const float*)d_in[4];
    const float* wv = (const float*)d_in[5];
    const float* bv = (const float*)d_in[6];
    const float* wm = (const float*)d_in[7];
    const float* bm = (const float*)d_in[8];
    const float* g1 = (const float*)d_in[9];
    const float* b1 = (const float*)d_in[10];
    const float* g2 = (const float*)d_in[11];
    const float* b2 = (const float*)d_in[12];
    float* out = (float*)d_out;

    unsigned char* base;
    cudaGetSymbolAddress((void**)&base, g_scratch);

    float* E    = (float*)(base + OFF_E);
    float* ATT  = (float*)(base + OFF_ATT);
    float* Y1   = (float*)(base + OFF_Y1);
    float* T    = (float*)(base + OFF_T);
    float* bqk  = (float*)(base + OFF_BQK);
    bf16 *xh   = (bf16*)(base + OFF_XH),   *xl   = (bf16*)(base + OFF_XL);
    bf16 *wqkh = (bf16*)(base + OFF_WQKH), *wqkl = (bf16*)(base + OFF_WQKL);
    bf16 *wvh  = (bf16*)(base + OFF_WVH),  *wvl  = (bf16*)(base + OFF_WVL);
    bf16 *wmh  = (bf16*)(base + OFF_WMH),  *wml  = (bf16*)(base + OFF_WML);
    bf16 *qkh  = (bf16*)(base + OFF_QKH),  *qkl  = (bf16*)(base + OFF_QKL);
    bf16 *vh   = (bf16*)(base + OFF_VH),   *vl   = (bf16*)(base + OFF_VL);
    bf16 *a2h  = (bf16*)(base + OFF_A2H),  *a2l  = (bf16*)(base + OFF_A2L);
    bf16 *y1h  = (bf16*)(base + OFF_Y1H),  *y1l  = (bf16*)(base + OFF_Y1L);

    cudaFuncSetAttribute(hgemm<false, 1, true>,
                         cudaFuncAttributeMaxDynamicSharedMemorySize, GEMM_DSMEM);
    cudaFuncSetAttribute(hgemm<false, 0, false>,
                         cudaFuncAttributeMaxDynamicSharedMemorySize, GEMM_DSMEM);
    cudaFuncSetAttribute(hgemm<true, 0, false>,
                         cudaFuncAttributeMaxDynamicSharedMemorySize, GEMM_DSMEM);
    cudaFuncSetAttribute(hgemm<false, 0, true>,
                         cudaFuncAttributeMaxDynamicSharedMemorySize, GEMM_DSMEM);

    // 0) conversions: x pair; transposed+split weights; packed qk bias
    conv_pair<<<(MTOT * CC / 4 + 255) / 256, 256>>>(x, xh, xl, MTOT * CC / 4);
    convw_t<<<(CC * RR + 255) / 256, 256>>>(wq, wqkh, wqkl, CC, RR, 0);
    convw_t<<<(CC * RR + 255) / 256, 256>>>(wk, wqkh, wqkl, CC, RR, 64);
    convw_t<<<(CC * CC + 255) / 256, 256>>>(wv, wvh, wvl, CC, CC, 0);
    convw_t<<<(CC * CC + 255) / 256, 256>>>(wm, wmh, wml, CC, CC, 0);
    packb<<<1, 64>>>(bq, bk, bqk);

    // 1) QK projection: [8192,512] @ wqk^T[128,512] -> QK pair [8192,128]
    hgemm<false, 1, true><<<dim3(2, MTOT / 128, 1), 256, GEMM_DSMEM>>>(
        xh, xl, CC, 0, wqkh, wqkl, CC, 0, bqk,
        nullptr, qkh, qkl, 128, 0, CC);

    // 2) V projection: -> V pair [8192,512]
    hgemm<false, 1, true><<<dim3(CC / 64, MTOT / 128, 1), 256, GEMM_DSMEM>>>(
        xh, xl, CC, 0, wvh, wvl, CC, 0, bv,
        nullptr, vh, vl, CC, 0, CC);

    // 3) scores: per batch E = Q @ K^T (Q/K strided slices of packed QK)
    hgemm<false, 0, false><<<dim3(NKEY / 64, NKEY / 128, BB), 256, GEMM_DSMEM>>>(
        qkh, qkl, 128, (long)NKEY * 128,
        qkh + 64, qkl + 64, 128, (long)NKEY * 128, nullptr,
        E, nullptr, nullptr, NKEY, (long)NKEY * NKEY, RR);

    // 4) softmax + key-depth fold -> A2 pair [B*2048, 256]
    softmax_fold<<<BB * NKEY, 256>>>(E, a2h, a2l);

    // 5) attn: per (b,d) slice A2[256,256] @ V[256,512] (NN) -> ATT [256,512]
    hgemm<true, 0, false><<<dim3(CC / 64, FF / 128, BB * DD), 256, GEMM_DSMEM>>>(
        a2h, a2l, FF, (long)FF * FF,
        vh, vl, CC, (long)FF * CC, nullptr,
        ATT, nullptr, nullptr, CC, (long)FF * CC, FF);

    // 6) y1 = LN(attn + x), emit pair
    add_ln<<<MTOT, 128>>>(ATT, x, g1, b1, Y1, y1h, y1l, 0);

    // 7) MLP: T = y1 @ wm^T + bm
    hgemm<false, 0, true><<<dim3(CC / 64, MTOT / 128, 1), 256, GEMM_DSMEM>>>(
        y1h, y1l, CC, 0, wmh, wml, CC, 0, bm,
        T, nullptr, nullptr, CC, 0, CC);

    // 8) out = LN(y1 + relu(T))
    add_ln<<<MTOT, 128>>>(Y1, T, g2, b2, out, nullptr, nullptr, 1);
}

// round 14
// speedup vs baseline: 2.3638x; 1.0956x over previous
#include <cuda_runtime.h>
#include <cuda_bf16.h>
#include <stdint.h>
#include <cstdint>
#include <math.h>

// Problem constants
#define BB 4
#define DD 8
#define FF 256
#define CC 512
#define RR 64
#define NKEY 2048            // D*F
#define MTOT 8192            // B*D*F
#define LN_EPS 1e-3f

typedef __nv_bfloat16 bf16;

// ---------------------------------------------------------------------------
// Scratch arena (static device memory; no allocations).
// ---------------------------------------------------------------------------
#define AL(x) (((x) + 255) & ~((size_t)255))
static const size_t OFF_ATT   = 0;
static const size_t OFF_Y1    = AL(OFF_ATT   + (size_t)MTOT*CC*4);
static const size_t OFF_T     = AL(OFF_Y1    + (size_t)MTOT*CC*4);
static const size_t OFF_XH    = AL(OFF_T     + (size_t)MTOT*CC*4);
static const size_t OFF_XL    = AL(OFF_XH    + (size_t)MTOT*CC*2);
static const size_t OFF_WH    = AL(OFF_XL    + (size_t)MTOT*CC*2);        // [640,512] w^T qkv
static const size_t OFF_WL    = AL(OFF_WH    + (size_t)640*CC*2);
static const size_t OFF_WMH   = AL(OFF_WL    + (size_t)640*CC*2);         // [512,512] w^T
static const size_t OFF_WML   = AL(OFF_WMH   + (size_t)CC*CC*2);
static const size_t OFF_QKVH  = AL(OFF_WML   + (size_t)CC*CC*2);          // [8192,640]
static const size_t OFF_QKVL  = AL(OFF_QKVH  + (size_t)MTOT*640*2);
static const size_t OFF_A2H   = AL(OFF_QKVL  + (size_t)MTOT*640*2);       // [8192,256]
static const size_t OFF_A2L   = AL(OFF_A2H   + (size_t)BB*NKEY*FF*2);
static const size_t OFF_Y1H   = AL(OFF_A2L   + (size_t)BB*NKEY*FF*2);
static const size_t OFF_Y1L   = AL(OFF_Y1H   + (size_t)MTOT*CC*2);
static const size_t OFF_BQKV  = AL(OFF_Y1L   + (size_t)MTOT*CC*2);        // f32 [640]
static const size_t SCRATCH_TOTAL = AL(OFF_BQKV + 640*4);

__device__ unsigned char g_scratch[SCRATCH_TOTAL];

// ---------------------------------------------------------------------------
// helpers
// ---------------------------------------------------------------------------
__device__ __forceinline__ uint32_t smem_u32(const void* p) {
    uint32_t a;
    asm("{ .reg .u64 t; cvta.to.shared.u64 t, %1; cvt.u32.u64 %0, t; }" : "=r"(a) : "l"(p));
    return a;
}
__device__ __forceinline__ void split2(float v, bf16& h, bf16& l) {
    h = __float2bfloat16(v);
    l = __float2bfloat16(v - __bfloat162float(h));
}
__device__ __forceinline__ unsigned pack2(bf16 a, bf16 b) {
    __nv_bfloat162 t(a, b);
    return *(unsigned*)&t;
}
__device__ __forceinline__ void ldsm_x4(unsigned r[4], uint32_t addr) {
    asm volatile("ldmatrix.sync.aligned.m8n8.x4.shared.b16 {%0,%1,%2,%3}, [%4];"
                 : "=r"(r[0]), "=r"(r[1]), "=r"(r[2]), "=r"(r[3]) : "r"(addr));
}
__device__ __forceinline__ void ldsm_x4t(unsigned r[4], uint32_t addr) {
    asm volatile("ldmatrix.sync.aligned.m8n8.x4.trans.shared.b16 {%0,%1,%2,%3}, [%4];"
                 : "=r"(r[0]), "=r"(r[1]), "=r"(r[2]), "=r"(r[3]) : "r"(addr));
}
__device__ __forceinline__ void mma_bf16(float c[4], const unsigned a[4], const unsigned b[2]) {
    asm volatile(
        "mma.sync.aligned.m16n8k16.row.col.f32.bf16.bf16.f32 "
        "{%0,%1,%2,%3}, {%4,%5,%6,%7}, {%8,%9}, {%0,%1,%2,%3};"
        : "+f"(c[0]), "+f"(c[1]), "+f"(c[2]), "+f"(c[3])
        : "r"(a[0]), "r"(a[1]), "r"(a[2]), "r"(a[3]), "r"(b[0]), "r"(b[1]));
}
__device__ __forceinline__ void cpa(uint32_t dst, const void* src) {
    asm volatile(
        "{ .reg .u64 g; cvta.to.global.u64 g, %1; cp.async.cg.shared.global [%0], [g], 16; }"
        :: "r"(dst), "l"(src) : "memory");
}
__device__ __forceinline__ void cp_commit() {
    asm volatile("cp.async.commit_group;" ::: "memory");
}
template<int N>
__device__ __forceinline__ void cp_wait() {
    asm volatile("cp.async.wait_group %0;" :: "n"(N) : "memory");
}

// ---------------------------------------------------------------------------
// HMMA GEMM, split-bf16 x3, fp32 accumulate, cp.async 3-stage pipeline.
//   NN=false: C[M,N] = A[M,K] @ B[N,K]^T   (B K-major)
//   NN=true : C[M,N] = A[M,K] @ B[K,N]     (B N-major, ldsm trans)
// Block tile 128x64, BK=32, 8 warps (4m x 2n), warp tile 32x32.
// OUTMODE: 0 = fp32 out, 1 = bf16 hi/lo pair out.
// ---------------------------------------------------------------------------
#define STAGE_BYTES 30720       // Ah 10240 + Al 10240 + B 10240(max)
#define NSTAGE 3
#define GEMM_DSMEM (NSTAGE * STAGE_BYTES + 128)

template<bool NN, int OUTMODE, bool BIAS>
__global__ __launch_bounds__(256, 2)
void hgemm(const bf16* __restrict__ Ah, const bf16* __restrict__ Al, int lda, long sA,
           const bf16* __restrict__ Bh, const bf16* __restrict__ Bl, int ldb, long sB,
           const float* __restrict__ bias,
           float* __restrict__ Cf, bf16* __restrict__ Ch, bf16* __restrict__ Cl,
           int ldc, long sC, int Kdim)
{
    extern __shared__ __align__(128) char dyn[];
    const int z = blockIdx.z;
    Ah += z * sA; Al += z * sA;
    Bh += z * sB; Bl += z * sB;
    if (OUTMODE == 0) Cf += z * sC;
    else { Ch += z * sC; Cl += z * sC; }

    const int tid  = threadIdx.x;
    const int lane = tid & 31;
    const int warp = tid >> 5;
    const int wm   = warp & 3;      // 0..3, m-quadrant
    const int wn   = warp >> 2;     // 0..1, n-half
    const int rowBase = blockIdx.y * 128;
    const int colBase = blockIdx.x * 64;

    uint32_t sb = smem_u32(dyn);
    sb = (sb + 127) & ~127u;

    float acc[2][4][4] = {};

    auto load = [&](int kt, int st) {
        const int k0 = kt * 32;
        const uint32_t stb = sb + st * STAGE_BYTES;
#pragma unroll
        for (int i = 0; i < 2; i++) {
            const int u = tid + i * 256;       // 0..511 16B-chunks
            const int r = u >> 2, c = u & 3;
            const uint32_t d = stb + r * 80 + c * 16;
            const long off = (long)(rowBase + r) * lda + k0 + c * 8;
            cpa(d,         Ah + off);
            cpa(d + 10240, Al + off);
        }
        if (!NN) {
            const int r = tid >> 2, c = tid & 3;     // 64 rows x 4 chunks
            const uint32_t d = stb + 20480 + r * 80 + c * 16;
            const long off = (long)(colBase + r) * ldb + k0 + c * 8;
            cpa(d,        Bh + off);
            cpa(d + 5120, Bl + off);
        } else {
            const int r = tid >> 3, c = tid & 7;     // 32 rows x 8 chunks
            const uint32_t d = stb + 20480 + r * 144 + c * 16;
            const long off = (long)(k0 + r) * ldb + colBase + c * 8;
            cpa(d,        Bh + off);
            cpa(d + 4608, Bl + off);
        }
        cp_commit();
    };

    auto compute = [&](int st) {
        const uint32_t stb = sb + st * STAGE_BYTES;
#pragma unroll
        for (int s = 0; s < 2; s++) {          // two k16 steps per chunk
            unsigned afh[2][4], afl[2][4], bh[4][2], bl[4][2];
#pragma unroll
            for (int mi = 0; mi < 2; mi++) {
                const uint32_t ad = stb + (wm * 32 + mi * 16 + (lane & 15)) * 80
                                  + s * 32 + (lane >> 4) * 16;
                ldsm_x4(afh[mi], ad);
                ldsm_x4(afl[mi], ad + 10240);
            }
#pragma unroll
            for (int pr = 0; pr < 2; pr++) {
                unsigned t[4];
                uint32_t bd;
                if (!NN) {
                    const int nrow = wn * 32 + pr * 16 + (lane & 7) + ((lane >> 4) & 1) * 8;
                    bd = stb + 20480 + nrow * 80 + s * 32 + ((lane >> 3) & 1) * 16;
                    ldsm_x4(t, bd);
                } else {
                    const int krow = s * 16 + (lane & 15);
                    bd = stb + 20480 + krow * 144
                       + (wn * 32 + pr * 16 + ((lane >> 4) & 1) * 8) * 2;
                    ldsm_x4t(t, bd);
                }
                bh[2*pr][0] = t[0]; bh[2*pr][1] = t[1];
                bh[2*pr+1][0] = t[2]; bh[2*pr+1][1] = t[3];
                if (!NN) ldsm_x4(t, bd + 5120); else ldsm_x4t(t, bd + 4608);
                bl[2*pr][0] = t[0]; bl[2*pr][1] = t[1];
                bl[2*pr+1][0] = t[2]; bl[2*pr+1][1] = t[3];
            }
#pragma unroll
            for (int mi = 0; mi < 2; mi++)
#pragma unroll
                for (int ni = 0; ni < 4; ni++) {
                    mma_bf16(acc[mi][ni], afh[mi], bh[ni]);   // hi*hi
                    mma_bf16(acc[mi][ni], afh[mi], bl[ni]);   // hi*lo
                    mma_bf16(acc[mi][ni], afl[mi], bh[ni]);   // lo*hi
                }
        }
    };

    const int nT = Kdim / 32;      // >= 2 for all our shapes
    load(0, 0);
    load(1, 1);
    if (nT > 2) load(2, 2);

    for (int kt = 0; kt < nT; kt++) {
        const int rem = nT - 1 - kt;
        if (rem >= 2)      cp_wait<2>();
        else if (rem == 1) cp_wait<1>();
        else               cp_wait<0>();
        __syncthreads();
        const int st = kt % NSTAGE;
        compute(st);
        __syncthreads();
        if (kt + 3 < nT) load(kt + 3, st);
    }

    const int g = lane >> 2, t4 = lane & 3;
#pragma unroll
    for (int ni = 0; ni < 4; ni++) {
        const int c = colBase + wn * 32 + ni * 8 + 2 * t4;
        float bx = 0.f, by = 0.f;
        if (BIAS) { bx = bias[c]; by = bias[c + 1]; }
#pragma unroll
        for (int mi = 0; mi < 2; mi++) {
            const int r0 = rowBase + wm * 32 + mi * 16 + g;
            const float v00 = acc[mi][ni][0] + bx, v01 = acc[mi][ni][1] + by;
            const float v10 = acc[mi][ni][2] + bx, v11 = acc[mi][ni][3] + by;
            if (OUTMODE == 0) {
                *(float2*)(Cf + (long)r0 * ldc + c)       = make_float2(v00, v01);
                *(float2*)(Cf + (long)(r0 + 8) * ldc + c) = make_float2(v10, v11);
            } else {
                bf16 h0, l0, h1, l1;
                split2(v00, h0, l0); split2(v01, h1, l1);
                *(unsigned*)(Ch + (long)r0 * ldc + c) = pack2(h0, h1);
                *(unsigned*)(Cl + (long)r0 * ldc + c) = pack2(l0, l1);
                split2(v10, h0, l0); split2(v11, h1, l1);
                *(unsigned*)(Ch + (long)(r0 + 8) * ldc + c) = pack2(h0, h1);
                *(unsigned*)(Cl + (long)(r0 + 8) * ldc + c) = pack2(l0, l1);
            }
        }
    }
}

// ---------------------------------------------------------------------------
// Fused scores + softmax (no max shift; |e|<~10 so exp is fp32-safe) + fold.
// One CTA = 64 query rows of one batch, loops over 16 key tiles of 128.
// Key tile kt covers jf range [(kt&1)*128, +128) (since jf = key % 256).
// acc[64][256] fp32 in smem accumulates sum_g exp(e); Z = row-sum of acc.
// Writes A2 bf16 hi/lo pair directly.
// ---------------------------------------------------------------------------
#define ACCP 264
#define FS_SQH 0
#define FS_SQL 9216
#define FS_SK  18432
#define FS_KST 36864
#define FS_KHL 18432
#define FS_ACC 92160
#define FS_ZP  159744
#define FS_ZI  160768
#define FS_DSMEM (161024 + 128)

__global__ __launch_bounds__(256, 1)
void fused_scores(const bf16* __restrict__ QKVh, const bf16* __restrict__ QKVl,
                  bf16* __restrict__ A2h, bf16* __restrict__ A2l)
{
    extern __shared__ __align__(128) char dyn[];
    const int z  = blockIdx.z;           // batch
    const int qt = blockIdx.x;           // query tile (64 rows)
    const long tokBase = (long)z * NKEY;

    const int tid  = threadIdx.x;
    const int lane = tid & 31;
    const int warp = tid >> 5;
    const int wm = warp & 1, wn = warp >> 1;     // 2m x 4n warp grid

    uint32_t raw = smem_u32(dyn);
    const uint32_t sb = (raw + 127) & ~127u;
    char* smp = dyn + (sb - raw);
    float* acc = (float*)(smp + FS_ACC);
    float* zp  = (float*)(smp + FS_ZP);
    float* zi  = (float*)(smp + FS_ZI);

    // zero acc
    for (int i = tid; i < 64 * ACCP; i += 256) acc[i] = 0.f;

    // load Q tile (64 rows x 64 dims, hi/lo), QKV cols 0..63
#pragma unroll
    for (int i = 0; i < 2; i++) {
        const int u = tid + i * 256;     // 0..511
        const int r = u >> 3, c = u & 7;
        const long src = (tokBase + (long)qt * 64 + r) * 640 + c * 8;
        cpa(sb + FS_SQH + r * 144 + c * 16, QKVh + src);
        cpa(sb + FS_SQL + r * 144 + c * 16, QKVl + src);
    }
    cp_commit();

    auto loadK = [&](int kt, int st) {
        const uint32_t stb = sb + FS_SK + st * FS_KST;
#pragma unroll
        for (int i = 0; i < 4; i++) {
            const int u = tid + i * 256;   // 0..1023
            const int r = u >> 3, c = u & 7;
            const long src = (tokBase + (long)kt * 128 + r) * 640 + 64 + c * 8;
            cpa(stb + r * 144 + c * 16,          QKVh + src);
            cpa(stb + FS_KHL + r * 144 + c * 16, QKVl + src);
        }
        cp_commit();
    };

    loadK(0, 0);
    loadK(1, 1);

    for (int kt = 0; kt < 16; kt++) {
        if (kt == 15) cp_wait<0>(); else cp_wait<1>();
        __syncthreads();

        float c[2][4][4] = {};
        const uint32_t stb = sb + FS_SK + (kt & 1) * FS_KST;
#pragma unroll
        for (int ks = 0; ks < 4; ks++) {
            unsigned ah[2][4], al[2][4], bh[4][2], bl[4][2];
#pragma unroll
            for (int mi = 0; mi < 2; mi++) {
                const uint32_t ad = sb + FS_SQH
                    + (wm * 32 + mi * 16 + (lane & 15)) * 144 + ks * 32 + (lane >> 4) * 16;
                ldsm_x4(ah[mi], ad);
                ldsm_x4(al[mi], ad + (FS_SQL - FS_SQH));
            }
#pragma unroll
            for (int pr = 0; pr < 2; pr++) {
                unsigned t[4];
                const int nrow = wn * 32 + pr * 16 + (lane & 7) + ((lane >> 4) & 1) * 8;
                const uint32_t bd = stb + nrow * 144 + ks * 32 + ((lane >> 3) & 1) * 16;
                ldsm_x4(t, bd);
                bh[2*pr][0] = t[0]; bh[2*pr][1] = t[1];
                bh[2*pr+1][0] = t[2]; bh[2*pr+1][1] = t[3];
                ldsm_x4(t, bd + FS_KHL);
                bl[2*pr][0] = t[0]; bl[2*pr][1] = t[1];
                bl[2*pr+1][0] = t[2]; bl[2*pr+1][1] = t[3];
            }
#pragma unroll
            for (int mi = 0; mi < 2; mi++)
#pragma unroll
                for (int ni = 0; ni < 4; ni++) {
                    mma_bf16(c[mi][ni], ah[mi], bh[ni]);
                    mma_bf16(c[mi][ni], ah[mi], bl[ni]);
                    mma_bf16(c[mi][ni], al[mi], bh[ni]);
                }
        }

        // exp + fold-accumulate (each acc element owned by exactly one thread)
        const int jfb = (kt & 1) * 128;
        const int g = lane >> 2, t4 = lane & 3;
#pragma unroll
        for (int mi = 0; mi < 2; mi++) {
            const int r0 = wm * 32 + mi * 16 + g;
#pragma unroll
            for (int ni = 0; ni < 4; ni++) {
                const int cl = jfb + wn * 32 + ni * 8 + 2 * t4;
                acc[r0 * ACCP + cl]           += __expf(c[mi][ni][0]);
                acc[r0 * ACCP + cl + 1]       += __expf(c[mi][ni][1]);
                acc[(r0 + 8) * ACCP + cl]     += __expf(c[mi][ni][2]);
                acc[(r0 + 8) * ACCP + cl + 1] += __expf(c[mi][ni][3]);
            }
        }
        __syncthreads();
        if (kt + 2 < 16) loadK(kt + 2, kt & 1);
    }

    // Z per row = sum over all 256 jf (covers all 2048 keys)
    {
        const int r = tid >> 2, q = tid & 3;
        float s = 0.f;
        const float* row = acc + r * ACCP + q * 64;
#pragma unroll 16
        for (int j = 0; j < 64; j++) s += row[j];
        zp[r * 4 + q] = s;
    }
    __syncthreads();
    if (tid < 64)
        zi[tid] = 1.f / (zp[tid*4] + zp[tid*4+1] + zp[tid*4+2] + zp[tid*4+3]);
    __syncthreads();

    // write A2 pair: 64 rows x 128 bf16x2
#pragma unroll 4
    for (int it = 0; it < 32; it++) {
        const int pi = it * 256 + tid;       // 0..8191
        const int r = pi >> 7, p = pi & 127;
        const float inv = zi[r];
        const float v0 = acc[r * ACCP + 2*p]     * inv;
        const float v1 = acc[r * ACCP + 2*p + 1] * inv;
        bf16 h0, l0, h1, l1;
        split2(v0, h0, l0); split2(v1, h1, l1);
        const long row = tokBase + (long)qt * 64 + r;
        *(unsigned*)(A2h + row * 256 + 2*p) = pack2(h0, h1);
        *(unsigned*)(A2l + row * 256 + 2*p) = pack2(l0, l1);
    }
}

// ---------------------------------------------------------------------------
// fp32 -> (bf16 hi, bf16 lo), float4 per thread
// ---------------------------------------------------------------------------
__global__ void conv_pair(const float* __restrict__ src,
                          bf16* __restrict__ h, bf16* __restrict__ l, int n4)
{
    int i = blockIdx.x * blockDim.x + threadIdx.x;
    if (i >= n4) return;
    float4 v = ((const float4*)src)[i];
    bf16 h0, l0, h1, l1, h2, l2, h3, l3;
    split2(v.x, h0, l0); split2(v.y, h1, l1);
    split2(v.z, h2, l2); split2(v.w, h3, l3);
    ((__nv_bfloat162*)h)[i * 2]     = __nv_bfloat162(h0, h1);
    ((__nv_bfloat162*)h)[i * 2 + 1] = __nv_bfloat162(h2, h3);
    ((__nv_bfloat162*)l)[i * 2]     = __nv_bfloat162(l0, l1);
    ((__nv_bfloat162*)l)[i * 2 + 1] = __nv_bfloat162(l2, l3);
}

// transpose + split weights: src[K][N] -> dst[(n+rowOff)][K] hi/lo
__global__ void convw_t(const float* __restrict__ src, bf16* __restrict__ h,
                        bf16* __restrict__ l, int Krows, int Ncols, int rowOff)
{
    int i = blockIdx.x * blockDim.x + threadIdx.x;
    if (i >= Krows * Ncols) return;
    int k = i / Ncols, n = i % Ncols;
    bf16 hh, ll;
    split2(src[i], hh, ll);
    long d = (long)(n + rowOff) * Krows + k;
    h[d] = hh; l[d] = ll;
}

__global__ void packb3(const float* __restrict__ a, const float* __restrict__ b,
                       const float* __restrict__ c, float* __restrict__ d)
{
    int i = threadIdx.x;   // 640 threads
    d[i] = (i < 64) ? a[i] : (i < 128) ? b[i - 64] : c[i - 128];
}

// ---------------------------------------------------------------------------
// out = LayerNorm(A + f(B)) * gamma + beta; f=relu if relu_b; optional bf16 pair.
// ---------------------------------------------------------------------------
__global__ void add_ln(const float* __restrict__ A, const float* __restrict__ B,
                       const float* __restrict__ gamma, const float* __restrict__ beta,
                       float* __restrict__ outF,
                       bf16* __restrict__ outH, bf16* __restrict__ outL,
                       int relu_b)
{
    const long row = blockIdx.x;
    const int t = threadIdx.x;  // 0..127

    float4 a4 = ((const float4*)(A + row * CC))[t];
    float4 b4 = ((const float4*)(B + row * CC))[t];
    if (relu_b) {
        b4.x = fmaxf(b4.x, 0.f);
        b4.y = fmaxf(b4.y, 0.f);
        b4.z = fmaxf(b4.z, 0.f);
        b4.w = fmaxf(b4.w, 0.f);
    }
    float x0 = a4.x + b4.x, x1 = a4.y + b4.y, x2 = a4.z + b4.z, x3 = a4.w + b4.w;

    float s  = x0 + x1 + x2 + x3;
    float sq = x0 * x0 + x1 * x1 + x2 * x2 + x3 * x3;
#pragma unroll
    for (int o = 16; o > 0; o >>= 1) {
        s  += __shfl_xor_sync(0xFFFFFFFFu, s,  o);
        sq += __shfl_xor_sync(0xFFFFFFFFu, sq, o);
    }
    __shared__ float ss[4], qq[4];
    const int w = t >> 5, l = t & 31;
    if (l == 0) { ss[w] = s; qq[w] = sq; }
    __syncthreads();
    s  = ss[0] + ss[1] + ss[2] + ss[3];
    sq = qq[0] + qq[1] + qq[2] + qq[3];

    const float mean = s * (1.f / CC);
    const float var  = sq * (1.f / CC) - mean * mean;
    const float r    = rsqrtf(var + LN_EPS);

    float4 g4  = ((const float4*)gamma)[t];
    float4 be4 = ((const float4*)beta)[t];
    float4 o4;
    o4.x = (x0 - mean) * r * g4.x + be4.x;
    o4.y = (x1 - mean) * r * g4.y + be4.y;
    o4.z = (x2 - mean) * r * g4.z + be4.z;
    o4.w = (x3 - mean) * r * g4.w + be4.w;
    ((float4*)(outF + row * CC))[t] = o4;

    if (outH) {
        bf16 h0, l0, h1, l1, h2, l2, h3, l3;
        split2(o4.x, h0, l0); split2(o4.y, h1, l1);
        split2(o4.z, h2, l2); split2(o4.w, h3, l3);
        long i = row * (CC / 2) + t * 2;
        ((__nv_bfloat162*)outH)[i]     = __nv_bfloat162(h0, h1);
        ((__nv_bfloat162*)outH)[i + 1] = __nv_bfloat162(h2, h3);
        ((__nv_bfloat162*)outL)[i]     = __nv_bfloat162(l0, l1);
        ((__nv_bfloat162*)outL)[i + 1] = __nv_bfloat162(l2, l3);
    }
}

// ---------------------------------------------------------------------------
extern "C" void kernel_launch(void* const* d_in, const int* in_sizes, int n_in,
                              void* d_out, int out_size)
{
    const float* x  = (const float*)d_in[0];
    const float* wq = (const float*)d_in[1];
    const float* bq = (const float*)d_in[2];
    const float* wk = (const float*)d_in[3];
    const float* bk = (const float*)d_in[4];
    const float* wv = (const float*)d_in[5];
    const float* bv = (const float*)d_in[6];
    const float* wm = (const float*)d_in[7];
    const float* bm = (const float*)d_in[8];
    const float* g1 = (const float*)d_in[9];
    const float* b1 = (const float*)d_in[10];
    const float* g2 = (const float*)d_in[11];
    const float* b2 = (const float*)d_in[12];
    float* out = (float*)d_out;

    unsigned char* base;
    cudaGetSymbolAddress((void**)&base, g_scratch);

    float* ATT  = (float*)(base + OFF_ATT);
    float* Y1   = (float*)(base + OFF_Y1);
    float* T    = (float*)(base + OFF_T);
    float* bqkv = (float*)(base + OFF_BQKV);
    bf16 *xh   = (bf16*)(base + OFF_XH),   *xl   = (bf16*)(base + OFF_XL);
    bf16 *wh   = (bf16*)(base + OFF_WH),   *wl   = (bf16*)(base + OFF_WL);
    bf16 *wmh  = (bf16*)(base + OFF_WMH),  *wml  = (bf16*)(base + OFF_WML);
    bf16 *qkvh = (bf16*)(base + OFF_QKVH), *qkvl = (bf16*)(base + OFF_QKVL);
    bf16 *a2h  = (bf16*)(base + OFF_A2H),  *a2l  = (bf16*)(base + OFF_A2L);
    bf16 *y1h  = (bf16*)(base + OFF_Y1H),  *y1l  = (bf16*)(base + OFF_Y1L);

    cudaFuncSetAttribute(hgemm<false, 1, true>,
                         cudaFuncAttributeMaxDynamicSharedMemorySize, GEMM_DSMEM);
    cudaFuncSetAttribute(hgemm<true, 0, false>,
                         cudaFuncAttributeMaxDynamicSharedMemorySize, GEMM_DSMEM);
    cudaFuncSetAttribute(hgemm<false, 0, true>,
                         cudaFuncAttributeMaxDynamicSharedMemorySize, GEMM_DSMEM);
    cudaFuncSetAttribute(fused_scores,
                         cudaFuncAttributeMaxDynamicSharedMemorySize, FS_DSMEM);

    // 0) conversions
    conv_pair<<<(MTOT * CC / 4 + 255) / 256, 256>>>(x, xh, xl, MTOT * CC / 4);
    convw_t<<<(CC * RR + 255) / 256, 256>>>(wq, wh, wl, CC, RR, 0);
    convw_t<<<(CC * RR + 255) / 256, 256>>>(wk, wh, wl, CC, RR, 64);
    convw_t<<<(CC * CC + 255) / 256, 256>>>(wv, wh, wl, CC, CC, 128);
    convw_t<<<(CC * CC + 255) / 256, 256>>>(wm, wmh, wml, CC, CC, 0);
    packb3<<<1, 640>>>(bq, bk, bv, bqkv);

    // 1) fused QKV projection: [8192,512] @ W'[640,512]^T -> QKV pair [8192,640]
    hgemm<false, 1, true><<<dim3(10, MTOT / 128, 1), 256, GEMM_DSMEM>>>(
        xh, xl, CC, 0, wh, wl, CC, 0, bqkv,
        nullptr, qkvh, qkvl, 640, 0, CC);

    // 2) fused scores + softmax + fold -> A2 pair [8192, 256]
    fused_scores<<<dim3(NKEY / 64, 1, BB), 256, FS_DSMEM>>>(qkvh, qkvl, a2h, a2l);

    // 3) attn: per (b,d) slice A2[256,256] @ V[256,512] (NN, strided V slice)
    hgemm<true, 0, false><<<dim3(CC / 64, FF / 128, BB * DD), 256, GEMM_DSMEM>>>(
        a2h, a2l, FF, (long)FF * FF,
        qkvh + 128, qkvl + 128, 640, (long)FF * 640, nullptr,
        ATT, nullptr, nullptr, CC, (long)FF * CC, FF);

    // 4) y1 = LN(attn + x), emit pair
    add_ln<<<MTOT, 128>>>(ATT, x, g1, b1, Y1, y1h, y1l, 0);

    // 5) MLP: T = y1 @ wm^T + bm
    hgemm<false, 0, true><<<dim3(CC / 64, MTOT / 128, 1), 256, GEMM_DSMEM>>>(
        y1h, y1l, CC, 0, wmh, wml, CC, 0, bm,
        T, nullptr, nullptr, CC, 0, CC);

    // 6) out = LN(y1 + relu(T))
    add_ln<<<MTOT, 128>>>(Y1, T, g2, b2, out, nullptr, nullptr, 1);
}

// round 16
// speedup vs baseline: 2.4499x; 1.0364x over previous
#include <cuda_runtime.h>
#include <cuda_bf16.h>
#include <stdint.h>
#include <cstdint>
#include <math.h>

// Problem constants
#define BB 4
#define DD 8
#define FF 256
#define CC 512
#define RR 64
#define NKEY 2048            // D*F
#define MTOT 8192            // B*D*F
#define LN_EPS 1e-3f

typedef __nv_bfloat16 bf16;

// ---------------------------------------------------------------------------
// Scratch arena (static device memory; no allocations).
// ---------------------------------------------------------------------------
#define AL(x) (((x) + 255) & ~((size_t)255))
static const size_t OFF_ATT   = 0;                                        // f32 [8192,512]
static const size_t OFF_T     = AL(OFF_ATT   + (size_t)MTOT*CC*4);        // f32 [8192,512]
static const size_t OFF_XH    = AL(OFF_T     + (size_t)MTOT*CC*4);
static const size_t OFF_XL    = AL(OFF_XH    + (size_t)MTOT*CC*2);
static const size_t OFF_WH    = AL(OFF_XL    + (size_t)MTOT*CC*2);        // [640,512] w^T qkv
static const size_t OFF_WL    = AL(OFF_WH    + (size_t)640*CC*2);
static const size_t OFF_WMH   = AL(OFF_WL    + (size_t)640*CC*2);         // [512,512] w^T
static const size_t OFF_WML   = AL(OFF_WMH   + (size_t)CC*CC*2);
static const size_t OFF_QKVH  = AL(OFF_WML   + (size_t)CC*CC*2);          // [8192,640]
static const size_t OFF_QKVL  = AL(OFF_QKVH  + (size_t)MTOT*640*2);
static const size_t OFF_A2H   = AL(OFF_QKVL  + (size_t)MTOT*640*2);       // [8192,256]
static const size_t OFF_A2L   = AL(OFF_A2H   + (size_t)BB*NKEY*FF*2);
static const size_t OFF_Y1H   = AL(OFF_A2L   + (size_t)BB*NKEY*FF*2);     // pair [8192,512]
static const size_t OFF_Y1L   = AL(OFF_Y1H   + (size_t)MTOT*CC*2);
static const size_t OFF_BQKV  = AL(OFF_Y1L   + (size_t)MTOT*CC*2);        // f32 [640]
static const size_t SCRATCH_TOTAL = AL(OFF_BQKV + 640*4);

__device__ unsigned char g_scratch[SCRATCH_TOTAL];

// ---------------------------------------------------------------------------
// helpers
// ---------------------------------------------------------------------------
__device__ __forceinline__ uint32_t smem_u32(const void* p) {
    uint32_t a;
    asm("{ .reg .u64 t; cvta.to.shared.u64 t, %1; cvt.u32.u64 %0, t; }" : "=r"(a) : "l"(p));
    return a;
}
__device__ __forceinline__ void split2(float v, bf16& h, bf16& l) {
    h = __float2bfloat16(v);
    l = __float2bfloat16(v - __bfloat162float(h));
}
__device__ __forceinline__ unsigned pack2(bf16 a, bf16 b) {
    __nv_bfloat162 t(a, b);
    return *(unsigned*)&t;
}
__device__ __forceinline__ void ldsm_x4(unsigned r[4], uint32_t addr) {
    asm volatile("ldmatrix.sync.aligned.m8n8.x4.shared.b16 {%0,%1,%2,%3}, [%4];"
                 : "=r"(r[0]), "=r"(r[1]), "=r"(r[2]), "=r"(r[3]) : "r"(addr));
}
__device__ __forceinline__ void ldsm_x4t(unsigned r[4], uint32_t addr) {
    asm volatile("ldmatrix.sync.aligned.m8n8.x4.trans.shared.b16 {%0,%1,%2,%3}, [%4];"
                 : "=r"(r[0]), "=r"(r[1]), "=r"(r[2]), "=r"(r[3]) : "r"(addr));
}
__device__ __forceinline__ void mma_bf16(float c[4], const unsigned a[4], const unsigned b[2]) {
    asm volatile(
        "mma.sync.aligned.m16n8k16.row.col.f32.bf16.bf16.f32 "
        "{%0,%1,%2,%3}, {%4,%5,%6,%7}, {%8,%9}, {%0,%1,%2,%3};"
        : "+f"(c[0]), "+f"(c[1]), "+f"(c[2]), "+f"(c[3])
        : "r"(a[0]), "r"(a[1]), "r"(a[2]), "r"(a[3]), "r"(b[0]), "r"(b[1]));
}
__device__ __forceinline__ void cpa(uint32_t dst, const void* src) {
    asm volatile(
        "{ .reg .u64 g; cvta.to.global.u64 g, %1; cp.async.cg.shared.global [%0], [g], 16; }"
        :: "r"(dst), "l"(src) : "memory");
}
__device__ __forceinline__ void cp_commit() {
    asm volatile("cp.async.commit_group;" ::: "memory");
}
template<int N>
__device__ __forceinline__ void cp_wait() {
    asm volatile("cp.async.wait_group %0;" :: "n"(N) : "memory");
}

// ---------------------------------------------------------------------------
// HMMA GEMM, split-bf16 x3, fp32 accumulate, cp.async 3-stage pipeline.
//   NN=false: C[M,N] = A[M,K] @ B[N,K]^T   (B K-major)
//   NN=true : C[M,N] = A[M,K] @ B[K,N]     (B N-major, ldsm trans)
// Block tile 128x64, BK=32, 8 warps (4m x 2n), warp tile 32x32.
// OUTMODE: 0 = fp32 out, 1 = bf16 hi/lo pair out.
// ---------------------------------------------------------------------------
#define STAGE_BYTES 30720       // Ah 10240 + Al 10240 + B 10240(max)
#define NSTAGE 3
#define GEMM_DSMEM (NSTAGE * STAGE_BYTES + 128)

template<bool NN, int OUTMODE, bool BIAS>
__global__ __launch_bounds__(256, 2)
void hgemm(const bf16* __restrict__ Ah, const bf16* __restrict__ Al, int lda, long sA,
           const bf16* __restrict__ Bh, const bf16* __restrict__ Bl, int ldb, long sB,
           const float* __restrict__ bias,
           float* __restrict__ Cf, bf16* __restrict__ Ch, bf16* __restrict__ Cl,
           int ldc, long sC, int Kdim)
{
    extern __shared__ __align__(128) char dyn[];
    const int z = blockIdx.z;
    Ah += z * sA; Al += z * sA;
    Bh += z * sB; Bl += z * sB;
    if (OUTMODE == 0) Cf += z * sC;
    else { Ch += z * sC; Cl += z * sC; }

    const int tid  = threadIdx.x;
    const int lane = tid & 31;
    const int warp = tid >> 5;
    const int wm   = warp & 3;      // 0..3, m-quadrant
    const int wn   = warp >> 2;     // 0..1, n-half
    const int rowBase = blockIdx.y * 128;
    const int colBase = blockIdx.x * 64;

    uint32_t sb = smem_u32(dyn);
    sb = (sb + 127) & ~127u;

    float acc[2][4][4] = {};

    auto load = [&](int kt, int st) {
        const int k0 = kt * 32;
        const uint32_t stb = sb + st * STAGE_BYTES;
#pragma unroll
        for (int i = 0; i < 2; i++) {
            const int u = tid + i * 256;       // 0..511 16B-chunks
            const int r = u >> 2, c = u & 3;
            const uint32_t d = stb + r * 80 + c * 16;
            const long off = (long)(rowBase + r) * lda + k0 + c * 8;
            cpa(d,         Ah + off);
            cpa(d + 10240, Al + off);
        }
        if (!NN) {
            const int r = tid >> 2, c = tid & 3;     // 64 rows x 4 chunks
            const uint32_t d = stb + 20480 + r * 80 + c * 16;
            const long off = (long)(colBase + r) * ldb + k0 + c * 8;
            cpa(d,        Bh + off);
            cpa(d + 5120, Bl + off);
        } else {
            const int r = tid >> 3, c = tid & 7;     // 32 rows x 8 chunks
            const uint32_t d = stb + 20480 + r * 144 + c * 16;
            const long off = (long)(k0 + r) * ldb + colBase + c * 8;
            cpa(d,        Bh + off);
            cpa(d + 4608, Bl + off);
        }
        cp_commit();
    };

    auto compute = [&](int st) {
        const uint32_t stb = sb + st * STAGE_BYTES;
#pragma unroll
        for (int s = 0; s < 2; s++) {          // two k16 steps per chunk
            unsigned afh[2][4], afl[2][4], bh[4][2], bl[4][2];
#pragma unroll
            for (int mi = 0; mi < 2; mi++) {
                const uint32_t ad = stb + (wm * 32 + mi * 16 + (lane & 15)) * 80
                                  + s * 32 + (lane >> 4) * 16;
                ldsm_x4(afh[mi], ad);
                ldsm_x4(afl[mi], ad + 10240);
            }
#pragma unroll
            for (int pr = 0; pr < 2; pr++) {
                unsigned t[4];
                uint32_t bd;
                if (!NN) {
                    const int nrow = wn * 32 + pr * 16 + (lane & 7) + ((lane >> 4) & 1) * 8;
                    bd = stb + 20480 + nrow * 80 + s * 32 + ((lane >> 3) & 1) * 16;
                    ldsm_x4(t, bd);
                } else {
                    const int krow = s * 16 + (lane & 15);
                    bd = stb + 20480 + krow * 144
                       + (wn * 32 + pr * 16 + ((lane >> 4) & 1) * 8) * 2;
                    ldsm_x4t(t, bd);
                }
                bh[2*pr][0] = t[0]; bh[2*pr][1] = t[1];
                bh[2*pr+1][0] = t[2]; bh[2*pr+1][1] = t[3];
                if (!NN) ldsm_x4(t, bd + 5120); else ldsm_x4t(t, bd + 4608);
                bl[2*pr][0] = t[0]; bl[2*pr][1] = t[1];
                bl[2*pr+1][0] = t[2]; bl[2*pr+1][1] = t[3];
            }
#pragma unroll
            for (int mi = 0; mi < 2; mi++)
#pragma unroll
                for (int ni = 0; ni < 4; ni++) {
                    mma_bf16(acc[mi][ni], afh[mi], bh[ni]);   // hi*hi
                    mma_bf16(acc[mi][ni], afh[mi], bl[ni]);   // hi*lo
                    mma_bf16(acc[mi][ni], afl[mi], bh[ni]);   // lo*hi
                }
        }
    };

    const int nT = Kdim / 32;      // >= 2 for all our shapes
    load(0, 0);
    load(1, 1);
    if (nT > 2) load(2, 2);

    for (int kt = 0; kt < nT; kt++) {
        const int rem = nT - 1 - kt;
        if (rem >= 2)      cp_wait<2>();
        else if (rem == 1) cp_wait<1>();
        else               cp_wait<0>();
        __syncthreads();
        const int st = kt % NSTAGE;
        compute(st);
        __syncthreads();
        if (kt + 3 < nT) load(kt + 3, st);
    }

    const int g = lane >> 2, t4 = lane & 3;
#pragma unroll
    for (int ni = 0; ni < 4; ni++) {
        const int c = colBase + wn * 32 + ni * 8 + 2 * t4;
        float bx = 0.f, by = 0.f;
        if (BIAS) { bx = bias[c]; by = bias[c + 1]; }
#pragma unroll
        for (int mi = 0; mi < 2; mi++) {
            const int r0 = rowBase + wm * 32 + mi * 16 + g;
            const float v00 = acc[mi][ni][0] + bx, v01 = acc[mi][ni][1] + by;
            const float v10 = acc[mi][ni][2] + bx, v11 = acc[mi][ni][3] + by;
            if (OUTMODE == 0) {
                *(float2*)(Cf + (long)r0 * ldc + c)       = make_float2(v00, v01);
                *(float2*)(Cf + (long)(r0 + 8) * ldc + c) = make_float2(v10, v11);
            } else {
                bf16 h0, l0, h1, l1;
                split2(v00, h0, l0); split2(v01, h1, l1);
                *(unsigned*)(Ch + (long)r0 * ldc + c) = pack2(h0, h1);
                *(unsigned*)(Cl + (long)r0 * ldc + c) = pack2(l0, l1);
                split2(v10, h0, l0); split2(v11, h1, l1);
                *(unsigned*)(Ch + (long)(r0 + 8) * ldc + c) = pack2(h0, h1);
                *(unsigned*)(Cl + (long)(r0 + 8) * ldc + c) = pack2(l0, l1);
            }
        }
    }
}

// ---------------------------------------------------------------------------
// Fused scores + softmax (no max shift; |e|<~10 so exp is fp32-safe) + fold.
// One CTA = 64 query rows of one batch, loops over 16 key tiles of 128.
// Key tile kt covers jf range [(kt&1)*128, +128) (since jf = key % 256).
// Fold accumulator lives in REGISTERS (each thread owns 64 fixed (row,jf)
// slots); dumped to smem once at the end for the Z reduction + output.
// ---------------------------------------------------------------------------
#define ACCP 264
#define FS_SQH 0
#define FS_SQL 9216
#define FS_SK  18432
#define FS_KST 36864
#define FS_KHL 18432
#define FS_ACC 92160
#define FS_ZP  159744
#define FS_ZI  160768
#define FS_DSMEM (161024 + 128)

__global__ __launch_bounds__(256, 1)
void fused_scores(const bf16* __restrict__ QKVh, const bf16* __restrict__ QKVl,
                  bf16* __restrict__ A2h, bf16* __restrict__ A2l)
{
    extern __shared__ __align__(128) char dyn[];
    const int z  = blockIdx.z;           // batch
    const int qt = blockIdx.x;           // query tile (64 rows)
    const long tokBase = (long)z * NKEY;

    const int tid  = threadIdx.x;
    const int lane = tid & 31;
    const int warp = tid >> 5;
    const int wm = warp & 1, wn = warp >> 1;     // 2m x 4n warp grid

    uint32_t raw = smem_u32(dyn);
    const uint32_t sb = (raw + 127) & ~127u;
    char* smp = dyn + (sb - raw);
    float* acc = (float*)(smp + FS_ACC);
    float* zp  = (float*)(smp + FS_ZP);
    float* zi  = (float*)(smp + FS_ZI);

    // register fold accumulator: [jf-half][mi][ni][elem]
    float racc[2][2][4][4] = {};

    // load Q tile (64 rows x 64 dims, hi/lo), QKV cols 0..63
#pragma unroll
    for (int i = 0; i < 2; i++) {
        const int u = tid + i * 256;     // 0..511
        const int r = u >> 3, c = u & 7;
        const long src = (tokBase + (long)qt * 64 + r) * 640 + c * 8;
        cpa(sb + FS_SQH + r * 144 + c * 16, QKVh + src);
        cpa(sb + FS_SQL + r * 144 + c * 16, QKVl + src);
    }
    cp_commit();

    auto loadK = [&](int kt, int st) {
        const uint32_t stb = sb + FS_SK + st * FS_KST;
#pragma unroll
        for (int i = 0; i < 4; i++) {
            const int u = tid + i * 256;   // 0..1023
            const int r = u >> 3, c = u & 7;
            const long src = (tokBase + (long)kt * 128 + r) * 640 + 64 + c * 8;
            cpa(stb + r * 144 + c * 16,          QKVh + src);
            cpa(stb + FS_KHL + r * 144 + c * 16, QKVl + src);
        }
        cp_commit();
    };

    loadK(0, 0);
    loadK(1, 1);

    for (int kt = 0; kt < 16; kt++) {
        if (kt == 15) cp_wait<0>(); else cp_wait<1>();
        __syncthreads();

        float c[2][4][4] = {};
        const uint32_t stb = sb + FS_SK + (kt & 1) * FS_KST;
#pragma unroll
        for (int ks = 0; ks < 4; ks++) {
            unsigned ah[2][4], al[2][4], bh[4][2], bl[4][2];
#pragma unroll
            for (int mi = 0; mi < 2; mi++) {
                const uint32_t ad = sb + FS_SQH
                    + (wm * 32 + mi * 16 + (lane & 15)) * 144 + ks * 32 + (lane >> 4) * 16;
                ldsm_x4(ah[mi], ad);
                ldsm_x4(al[mi], ad + (FS_SQL - FS_SQH));
            }
#pragma unroll
            for (int pr = 0; pr < 2; pr++) {
                unsigned t[4];
                const int nrow = wn * 32 + pr * 16 + (lane & 7) + ((lane >> 4) & 1) * 8;
                const uint32_t bd = stb + nrow * 144 + ks * 32 + ((lane >> 3) & 1) * 16;
                ldsm_x4(t, bd);
                bh[2*pr][0] = t[0]; bh[2*pr][1] = t[1];
                bh[2*pr+1][0] = t[2]; bh[2*pr+1][1] = t[3];
                ldsm_x4(t, bd + FS_KHL);
                bl[2*pr][0] = t[0]; bl[2*pr][1] = t[1];
                bl[2*pr+1][0] = t[2]; bl[2*pr+1][1] = t[3];
            }
#pragma unroll
            for (int mi = 0; mi < 2; mi++)
#pragma unroll
                for (int ni = 0; ni < 4; ni++) {
                    mma_bf16(c[mi][ni], ah[mi], bh[ni]);
                    mma_bf16(c[mi][ni], ah[mi], bl[ni]);
                    mma_bf16(c[mi][ni], al[mi], bh[ni]);
                }
        }

        // exp + fold into registers (same slot every other tile)
        const int jh = kt & 1;
#pragma unroll
        for (int mi = 0; mi < 2; mi++)
#pragma unroll
            for (int ni = 0; ni < 4; ni++)
#pragma unroll
                for (int e = 0; e < 4; e++)
                    racc[jh][mi][ni][e] += __expf(c[mi][ni][e]);

        __syncthreads();
        if (kt + 2 < 16) loadK(kt + 2, kt & 1);
    }

    // dump register fold to smem acc
    {
        const int g = lane >> 2, t4 = lane & 3;
#pragma unroll
        for (int jh = 0; jh < 2; jh++)
#pragma unroll
            for (int mi = 0; mi < 2; mi++) {
                const int r0 = wm * 32 + mi * 16 + g;
#pragma unroll
                for (int ni = 0; ni < 4; ni++) {
                    const int cl = jh * 128 + wn * 32 + ni * 8 + 2 * t4;
                    acc[r0 * ACCP + cl]           = racc[jh][mi][ni][0];
                    acc[r0 * ACCP + cl + 1]       = racc[jh][mi][ni][1];
                    acc[(r0 + 8) * ACCP + cl]     = racc[jh][mi][ni][2];
                    acc[(r0 + 8) * ACCP + cl + 1] = racc[jh][mi][ni][3];
                }
            }
    }
    __syncthreads();

    // Z per row = sum over all 256 jf (covers all 2048 keys)
    {
        const int r = tid >> 2, q = tid & 3;
        float s = 0.f;
        const float* row = acc + r * ACCP + q * 64;
#pragma unroll 16
        for (int j = 0; j < 64; j++) s += row[j];
        zp[r * 4 + q] = s;
    }
    __syncthreads();
    if (tid < 64)
        zi[tid] = 1.f / (zp[tid*4] + zp[tid*4+1] + zp[tid*4+2] + zp[tid*4+3]);
    __syncthreads();

    // write A2 pair: 64 rows x 128 bf16x2
#pragma unroll 4
    for (int it = 0; it < 32; it++) {
        const int pi = it * 256 + tid;       // 0..8191
        const int r = pi >> 7, p = pi & 127;
        const float inv = zi[r];
        const float v0 = acc[r * ACCP + 2*p]     * inv;
        const float v1 = acc[r * ACCP + 2*p + 1] * inv;
        bf16 h0, l0, h1, l1;
        split2(v0, h0, l0); split2(v1, h1, l1);
        const long row = tokBase + (long)qt * 64 + r;
        *(unsigned*)(A2h + row * 256 + 2*p) = pack2(h0, h1);
        *(unsigned*)(A2l + row * 256 + 2*p) = pack2(l0, l1);
    }
}

// ---------------------------------------------------------------------------
// fp32 -> (bf16 hi, bf16 lo), float4 per thread
// ---------------------------------------------------------------------------
__global__ void conv_pair(const float* __restrict__ src,
                          bf16* __restrict__ h, bf16* __restrict__ l, int n4)
{
    int i = blockIdx.x * blockDim.x + threadIdx.x;
    if (i >= n4) return;
    float4 v = ((const float4*)src)[i];
    bf16 h0, l0, h1, l1, h2, l2, h3, l3;
    split2(v.x, h0, l0); split2(v.y, h1, l1);
    split2(v.z, h2, l2); split2(v.w, h3, l3);
    ((__nv_bfloat162*)h)[i * 2]     = __nv_bfloat162(h0, h1);
    ((__nv_bfloat162*)h)[i * 2 + 1] = __nv_bfloat162(h2, h3);
    ((__nv_bfloat162*)l)[i * 2]     = __nv_bfloat162(l0, l1);
    ((__nv_bfloat162*)l)[i * 2 + 1] = __nv_bfloat162(l2, l3);
}

// ---------------------------------------------------------------------------
// Tiled transpose + split: src[K][N] f32 -> dst[(n+rowOff)][K] bf16 hi/lo.
// 32x32 f32 smem tile; coalesced float4 reads and uint2 pair writes.
// ---------------------------------------------------------------------------
__global__ void convw_t2(const float* __restrict__ src, bf16* __restrict__ h,
                         bf16* __restrict__ l, int Krows, int Ncols, int rowOff)
{
    __shared__ float tile[32][33];
    const int kb = blockIdx.y * 32, nb = blockIdx.x * 32;
    const int t = threadIdx.x;            // 0..255
    {
        const int r = t >> 3, c4 = (t & 7) * 4;
        float4 v = *(const float4*)(src + (long)(kb + r) * Ncols + nb + c4);
        tile[r][c4 + 0] = v.x;
        tile[r][c4 + 1] = v.y;
        tile[r][c4 + 2] = v.z;
        tile[r][c4 + 3] = v.w;
    }
    __syncthreads();
    {
        const int n = t >> 3, k4 = (t & 7) * 4;
        bf16 hh[4], ll[4];
#pragma unroll
        for (int i = 0; i < 4; i++)
            split2(tile[k4 + i][n], hh[i], ll[i]);
        const long d = (long)(rowOff + nb + n) * Krows + kb + k4;
        *(uint2*)(h + d) = make_uint2(pack2(hh[0], hh[1]), pack2(hh[2], hh[3]));
        *(uint2*)(l + d) = make_uint2(pack2(ll[0], ll[1]), pack2(ll[2], ll[3]));
    }
}

__global__ void packb3(const float* __restrict__ a, const float* __restrict__ b,
                       const float* __restrict__ c, float* __restrict__ d)
{
    int i = threadIdx.x;   // 640 threads
    d[i] = (i < 64) ? a[i] : (i < 128) ? b[i - 64] : c[i - 128];
}

// ---------------------------------------------------------------------------
// ln1: y1 = LN(ATT + x); emits bf16 hi/lo pair ONLY (no f32).
// ---------------------------------------------------------------------------
__global__ void ln_fuse1(const float* __restrict__ A, const float* __restrict__ B,
                         const float* __restrict__ gamma, const float* __restrict__ beta,
                         bf16* __restrict__ outH, bf16* __restrict__ outL)
{
    const long row = blockIdx.x;
    const int t = threadIdx.x;  // 0..127

    float4 a4 = ((const float4*)(A + row * CC))[t];
    float4 b4 = ((const float4*)(B + row * CC))[t];
    float x0 = a4.x + b4.x, x1 = a4.y + b4.y, x2 = a4.z + b4.z, x3 = a4.w + b4.w;

    float s  = x0 + x1 + x2 + x3;
    float sq = x0 * x0 + x1 * x1 + x2 * x2 + x3 * x3;
#pragma unroll
    for (int o = 16; o > 0; o >>= 1) {
        s  += __shfl_xor_sync(0xFFFFFFFFu, s,  o);
        sq += __shfl_xor_sync(0xFFFFFFFFu, sq, o);
    }
    __shared__ float ss[4], qq[4];
    const int w = t >> 5, l = t & 31;
    if (l == 0) { ss[w] = s; qq[w] = sq; }
    __syncthreads();
    s  = ss[0] + ss[1] + ss[2] + ss[3];
    sq = qq[0] + qq[1] + qq[2] + qq[3];

    const float mean = s * (1.f / CC);
    const float var  = sq * (1.f / CC) - mean * mean;
    const float r    = rsqrtf(var + LN_EPS);

    float4 g4  = ((const float4*)gamma)[t];
    float4 be4 = ((const float4*)beta)[t];
    float o0 = (x0 - mean) * r * g4.x + be4.x;
    float o1 = (x1 - mean) * r * g4.y + be4.y;
    float o2 = (x2 - mean) * r * g4.z + be4.z;
    float o3 = (x3 - mean) * r * g4.w + be4.w;

    bf16 h0, l0, h1, l1, h2, l2, h3, l3;
    split2(o0, h0, l0); split2(o1, h1, l1);
    split2(o2, h2, l2); split2(o3, h3, l3);
    long i = row * (CC / 2) + t * 2;
    ((__nv_bfloat162*)outH)[i]     = __nv_bfloat162(h0, h1);
    ((__nv_bfloat162*)outH)[i + 1] = __nv_bfloat162(h2, h3);
    ((__nv_bfloat162*)outL)[i]     = __nv_bfloat162(l0, l1);
    ((__nv_bfloat162*)outL)[i + 1] = __nv_bfloat162(l2, l3);
}

// ---------------------------------------------------------------------------
// ln2: out = LN(y1 + relu(T)); y1 read as bf16 pair (h+l reconstruct); f32 out.
// ---------------------------------------------------------------------------
__global__ void ln_fuse2(const bf16* __restrict__ Ah, const bf16* __restrict__ Al,
                         const float* __restrict__ B,
                         const float* __restrict__ gamma, const float* __restrict__ beta,
                         float* __restrict__ outF)
{
    const long row = blockIdx.x;
    const int t = threadIdx.x;  // 0..127

    uint2 hu = ((const uint2*)(Ah + row * CC))[t];
    uint2 lu = ((const uint2*)(Al + row * CC))[t];
    __nv_bfloat162 h01 = *(__nv_bfloat162*)&hu.x, h23 = *(__nv_bfloat162*)&hu.y;
    __nv_bfloat162 l01 = *(__nv_bfloat162*)&lu.x, l23 = *(__nv_bfloat162*)&lu.y;
    float a0 = __bfloat162float(h01.x) + __bfloat162float(l01.x);
    float a1 = __bfloat162float(h01.y) + __bfloat162float(l01.y);
    float a2 = __bfloat162float(h23.x) + __bfloat162float(l23.x);
    float a3 = __bfloat162float(h23.y) + __bfloat162float(l23.y);

    float4 b4 = ((const float4*)(B + row * CC))[t];
    float x0 = a0 + fmaxf(b4.x, 0.f);
    float x1 = a1 + fmaxf(b4.y, 0.f);
    float x2 = a2 + fmaxf(b4.z, 0.f);
    float x3 = a3 + fmaxf(b4.w, 0.f);

    float s  = x0 + x1 + x2 + x3;
    float sq = x0 * x0 + x1 * x1 + x2 * x2 + x3 * x3;
#pragma unroll
    for (int o = 16; o > 0; o >>= 1) {
        s  += __shfl_xor_sync(0xFFFFFFFFu, s,  o);
        sq += __shfl_xor_sync(0xFFFFFFFFu, sq, o);
    }
    __shared__ float ss[4], qq[4];
    const int w = t >> 5, l = t & 31;
    if (l == 0) { ss[w] = s; qq[w] = sq; }
    __syncthreads();
    s  = ss[0] + ss[1] + ss[2] + ss[3];
    sq = qq[0] + qq[1] + qq[2] + qq[3];

    const float mean = s * (1.f / CC);
    const float var  = sq * (1.f / CC) - mean * mean;
    const float r    = rsqrtf(var + LN_EPS);

    float4 g4  = ((const float4*)gamma)[t];
    float4 be4 = ((const float4*)beta)[t];
    float4 o4;
    o4.x = (x0 - mean) * r * g4.x + be4.x;
    o4.y = (x1 - mean) * r * g4.y + be4.y;
    o4.z = (x2 - mean) * r * g4.z + be4.z;
    o4.w = (x3 - mean) * r * g4.w + be4.w;
    ((float4*)(outF + row * CC))[t] = o4;
}

// ---------------------------------------------------------------------------
extern "C" void kernel_launch(void* const* d_in, const int* in_sizes, int n_in,
                              void* d_out, int out_size)
{
    const float* x  = (const float*)d_in[0];
    const float* wq = (const float*)d_in[1];
    const float* bq = (const float*)d_in[2];
    const float* wk = (const float*)d_in[3];
    const float* bk = (const float*)d_in[4];
    const float* wv = (const float*)d_in[5];
    const float* bv = (const float*)d_in[6];
    const float* wm = (const float*)d_in[7];
    const float* bm = (const float*)d_in[8];
    const float* g1 = (const float*)d_in[9];
    const float* b1 = (const float*)d_in[10];
    const float* g2 = (const float*)d_in[11];
    const float* b2 = (const float*)d_in[12];
    float* out = (float*)d_out;

    unsigned char* base;
    cudaGetSymbolAddress((void**)&base, g_scratch);

    float* ATT  = (float*)(base + OFF_ATT);
    float* T    = (float*)(base + OFF_T);
    float* bqkv = (float*)(base + OFF_BQKV);
    bf16 *xh   = (bf16*)(base + OFF_XH),   *xl   = (bf16*)(base + OFF_XL);
    bf16 *wh   = (bf16*)(base + OFF_WH),   *wl   = (bf16*)(base + OFF_WL);
    bf16 *wmh  = (bf16*)(base + OFF_WMH),  *wml  = (bf16*)(base + OFF_WML);
    bf16 *qkvh = (bf16*)(base + OFF_QKVH), *qkvl = (bf16*)(base + OFF_QKVL);
    bf16 *a2h  = (bf16*)(base + OFF_A2H),  *a2l  = (bf16*)(base + OFF_A2L);
    bf16 *y1h  = (bf16*)(base + OFF_Y1H),  *y1l  = (bf16*)(base + OFF_Y1L);

    cudaFuncSetAttribute(hgemm<false, 1, true>,
                         cudaFuncAttributeMaxDynamicSharedMemorySize, GEMM_DSMEM);
    cudaFuncSetAttribute(hgemm<true, 0, false>,
                         cudaFuncAttributeMaxDynamicSharedMemorySize, GEMM_DSMEM);
    cudaFuncSetAttribute(hgemm<false, 0, true>,
                         cudaFuncAttributeMaxDynamicSharedMemorySize, GEMM_DSMEM);
    cudaFuncSetAttribute(fused_scores,
                         cudaFuncAttributeMaxDynamicSharedMemorySize, FS_DSMEM);

    // 0) conversions (tiled transpose for weights)
    conv_pair<<<(MTOT * CC / 4 + 255) / 256, 256>>>(x, xh, xl, MTOT * CC / 4);
    convw_t2<<<dim3(RR / 32, CC / 32), 256>>>(wq, wh, wl, CC, RR, 0);
    convw_t2<<<dim3(RR / 32, CC / 32), 256>>>(wk, wh, wl, CC, RR, 64);
    convw_t2<<<dim3(CC / 32, CC / 32), 256>>>(wv, wh, wl, CC, CC, 128);
    convw_t2<<<dim3(CC / 32, CC / 32), 256>>>(wm, wmh, wml, CC, CC, 0);
    packb3<<<1, 640>>>(bq, bk, bv, bqkv);

    // 1) fused QKV projection: [8192,512] @ W'[640,512]^T -> QKV pair [8192,640]
    hgemm<false, 1, true><<<dim3(10, MTOT / 128, 1), 256, GEMM_DSMEM>>>(
        xh, xl, CC, 0, wh, wl, CC, 0, bqkv,
        nullptr, qkvh, qkvl, 640, 0, CC);

    // 2) fused scores + softmax + fold -> A2 pair [8192, 256]
    fused_scores<<<dim3(NKEY / 64, 1, BB), 256, FS_DSMEM>>>(qkvh, qkvl, a2h, a2l);

    // 3) attn: per (b,d) slice A2[256,256] @ V[256,512] (NN, strided V slice)
    hgemm<true, 0, false><<<dim3(CC / 64, FF / 128, BB * DD), 256, GEMM_DSMEM>>>(
        a2h, a2l, FF, (long)FF * FF,
        qkvh + 128, qkvl + 128, 640, (long)FF * 640, nullptr,
        ATT, nullptr, nullptr, CC, (long)FF * CC, FF);

    // 4) y1 = LN(attn + x) -> pair only
    ln_fuse1<<<MTOT, 128>>>(ATT, x, g1, b1, y1h, y1l);

    // 5) MLP: T = y1 @ wm^T + bm
    hgemm<false, 0, true><<<dim3(CC / 64, MTOT / 128, 1), 256, GEMM_DSMEM>>>(
        y1h, y1l, CC, 0, wmh, wml, CC, 0, bm,
        T, nullptr, nullptr, CC, 0, CC);

    // 6) out = LN(y1 + relu(T))
    ln_fuse2<<<MTOT, 128>>>(y1h, y1l, T, g2, b2, out);
}